// round 1
// baseline (speedup 1.0000x reference)
#include <cuda_runtime.h>
#include <cuda_bf16.h>

// Problem constants
#define BB 4
#define TT 2048
#define CC 1024
#define HH 16
#define DD 64
#define FFD 4096
#define NTOK (BB*TT)          // 8192

// ---------------- scratch (device globals; no allocation allowed) -----------
__device__ float g_ln   [NTOK * CC];        // 32 MB (reused for LN1 and LN2)
__device__ float g_q    [BB*HH * TT * DD];  // 32 MB
__device__ float g_k    [BB*HH * TT * DD];  // 32 MB
__device__ float g_v    [BB*HH * TT * DD];  // 32 MB
__device__ float g_attnc[NTOK * CC];        // 32 MB  (concat heads, [B,T,H*D])
__device__ float g_x1   [NTOK * CC];        // 32 MB  (after attention residual)
__device__ float g_ff1  [NTOK * FFD];       // 128 MB

// ---------------- block reductions ------------------------------------------
__device__ __forceinline__ float blockSumf(float v, float* red) {
    int lane = threadIdx.x & 31, w = threadIdx.x >> 5, nw = blockDim.x >> 5;
    __syncthreads();                 // protect red reuse across calls
#pragma unroll
    for (int o = 16; o > 0; o >>= 1) v += __shfl_xor_sync(0xffffffffu, v, o);
    if (lane == 0) red[w] = v;
    __syncthreads();
    if (w == 0) {
        float t = (lane < nw) ? red[lane] : 0.f;
#pragma unroll
        for (int o = 16; o > 0; o >>= 1) t += __shfl_xor_sync(0xffffffffu, t, o);
        if (lane == 0) red[0] = t;
    }
    __syncthreads();
    return red[0];
}

__device__ __forceinline__ float blockMaxf(float v, float* red) {
    int lane = threadIdx.x & 31, w = threadIdx.x >> 5, nw = blockDim.x >> 5;
    __syncthreads();
#pragma unroll
    for (int o = 16; o > 0; o >>= 1) v = fmaxf(v, __shfl_xor_sync(0xffffffffu, v, o));
    if (lane == 0) red[w] = v;
    __syncthreads();
    if (w == 0) {
        float t = (lane < nw) ? red[lane] : -1e30f;
#pragma unroll
        for (int o = 16; o > 0; o >>= 1) t = fmaxf(t, __shfl_xor_sync(0xffffffffu, t, o));
        if (lane == 0) red[0] = t;
    }
    __syncthreads();
    return red[0];
}

// ---------------- LayerNorm over C=1024, one block per row ------------------
__global__ void __launch_bounds__(256) ln_kernel(
    const float* __restrict__ x, const float* __restrict__ g,
    const float* __restrict__ be, float* __restrict__ out)
{
    __shared__ float red[8];
    size_t row = blockIdx.x;
    const float* xr = x + row * CC;
    float* orow = out + row * CC;
    float v[4], s = 0.f, s2 = 0.f;
#pragma unroll
    for (int i = 0; i < 4; i++) {
        int idx = threadIdx.x + i * 256;
        v[i] = xr[idx];
        s += v[i];
        s2 += v[i] * v[i];
    }
    s  = blockSumf(s, red);
    s2 = blockSumf(s2, red);
    float mu  = s * (1.f / CC);
    float var = s2 * (1.f / CC) - mu * mu;
    float rstd = rsqrtf(var + 1e-5f);
#pragma unroll
    for (int i = 0; i < 4; i++) {
        int idx = threadIdx.x + i * 256;
        orow[idx] = (v[i] - mu) * rstd * g[idx] + be[idx];
    }
}

// ---------------- generic SGEMM: 128x128 tile, BK=8, 8x8 per thread ---------
// C[M,N] = A[M,K] @ B[K,N] (+ epilogue). M%128==0, N%128==0, K%8==0.
// EPI: 0 = plain, 1 = +bias[c] + res[r,c], 2 = relu(. + bias[c])
template <int EPI>
__global__ void __launch_bounds__(256) sgemm128(
    const float* __restrict__ A, const float* __restrict__ B,
    float* __restrict__ C, int M, int N, int K,
    const float* __restrict__ bias, const float* __restrict__ res)
{
    __shared__ float As[8][128];
    __shared__ float Bs[8][128];
    int tid = threadIdx.x;
    int arow = tid >> 1, acol = (tid & 1) << 2;
    int brow = tid >> 5, bcol = (tid & 31) << 2;
    int ty = tid >> 4, tx = tid & 15;

    const float* Ap = A + ((size_t)(blockIdx.y * 128 + arow)) * K + acol;
    const float* Bp = B + (size_t)brow * N + blockIdx.x * 128 + bcol;

    float acc[8][8] = {};
    for (int k0 = 0; k0 < K; k0 += 8) {
        float4 a4 = *(const float4*)(Ap + k0);
        As[acol + 0][arow] = a4.x;
        As[acol + 1][arow] = a4.y;
        As[acol + 2][arow] = a4.z;
        As[acol + 3][arow] = a4.w;
        *(float4*)&Bs[brow][bcol] = *(const float4*)(Bp + (size_t)k0 * N);
        __syncthreads();
#pragma unroll
        for (int kk = 0; kk < 8; kk++) {
            float ar[8], br[8];
            *(float4*)(ar)     = *(const float4*)&As[kk][ty * 8];
            *(float4*)(ar + 4) = *(const float4*)&As[kk][ty * 8 + 4];
            *(float4*)(br)     = *(const float4*)&Bs[kk][tx * 8];
            *(float4*)(br + 4) = *(const float4*)&Bs[kk][tx * 8 + 4];
#pragma unroll
            for (int i = 0; i < 8; i++)
#pragma unroll
                for (int j = 0; j < 8; j++)
                    acc[i][j] += ar[i] * br[j];
        }
        __syncthreads();
    }

    int r0 = blockIdx.y * 128 + ty * 8;
    int c0 = blockIdx.x * 128 + tx * 8;
#pragma unroll
    for (int i = 0; i < 8; i++) {
        size_t ro = (size_t)(r0 + i) * N;
#pragma unroll
        for (int j = 0; j < 8; j++) {
            float vv = acc[i][j];
            int c = c0 + j;
            if (EPI == 1) vv += bias[c] + res[ro + c];
            else if (EPI == 2) vv = fmaxf(vv + bias[c], 0.f);
            C[ro + c] = vv;
        }
    }
}

// ---------------- QKV batched GEMM: per (b,h,sel), M=2048,N=64,K=1024 -------
// grid: (T/128, 3, B*H), block 256, 128x64 tile, 8x4 per thread
__global__ void __launch_bounds__(256) qkv_kernel(
    const float* __restrict__ LN,
    const float* __restrict__ Wq, const float* __restrict__ Wk,
    const float* __restrict__ Wv,
    float* __restrict__ qo, float* __restrict__ ko, float* __restrict__ vo)
{
    __shared__ float As[8][128];
    __shared__ float Bs[8][64];
    int tid = threadIdx.x;
    int bh = blockIdx.z, b = bh >> 4, h = bh & 15;

    const float* W;
    float* O;
    if (blockIdx.y == 0)      { W = Wq; O = qo; }
    else if (blockIdx.y == 1) { W = Wk; O = ko; }
    else                      { W = Wv; O = vo; }
    W += (size_t)h * CC * DD;
    O += (size_t)bh * TT * DD;

    int arow = tid >> 1, acol = (tid & 1) << 2;
    const float* Ap = LN + ((size_t)b * TT + blockIdx.x * 128 + arow) * CC + acol;
    int ty = tid >> 4, tx = tid & 15;

    float acc[8][4] = {};
    for (int k0 = 0; k0 < CC; k0 += 8) {
        float4 a4 = *(const float4*)(Ap + k0);
        As[acol + 0][arow] = a4.x;
        As[acol + 1][arow] = a4.y;
        As[acol + 2][arow] = a4.z;
        As[acol + 3][arow] = a4.w;
        if (tid < 128) {
            *(float4*)&Bs[tid >> 4][(tid & 15) << 2] =
                *(const float4*)(W + (size_t)(k0 + (tid >> 4)) * DD + ((tid & 15) << 2));
        }
        __syncthreads();
#pragma unroll
        for (int kk = 0; kk < 8; kk++) {
            float ar[8], br[4];
            *(float4*)(ar)     = *(const float4*)&As[kk][ty * 8];
            *(float4*)(ar + 4) = *(const float4*)&As[kk][ty * 8 + 4];
            *(float4*)(br)     = *(const float4*)&Bs[kk][tx * 4];
#pragma unroll
            for (int i = 0; i < 8; i++)
#pragma unroll
                for (int j = 0; j < 4; j++)
                    acc[i][j] += ar[i] * br[j];
        }
        __syncthreads();
    }
    int r0 = blockIdx.x * 128 + ty * 8;
#pragma unroll
    for (int i = 0; i < 8; i++)
#pragma unroll
        for (int j = 0; j < 4; j++)
            O[(size_t)(r0 + i) * DD + tx * 4 + j] = acc[i][j];
}

// ---------------- attention: one block per (b,h,t), causal softmax ----------
// scores row in SMEM (<=2048), K staged in padded SMEM tiles, V from L2.
__global__ void __launch_bounds__(128) attn_kernel(
    const float* __restrict__ q, const float* __restrict__ k,
    const float* __restrict__ v, float* __restrict__ attnc)
{
    __shared__ float qs[DD];
    __shared__ float ks[128 * 65];
    __shared__ float sc[TT];
    __shared__ float red[4];
    __shared__ float accs[128];

    int t = blockIdx.x, bh = blockIdx.y;
    int tid = threadIdx.x;
    const float* qp = q + ((size_t)bh * TT + t) * DD;
    const float* kb = k + (size_t)bh * TT * DD;
    const float* vb = v + (size_t)bh * TT * DD;
    int len = t + 1;

    if (tid < DD) qs[tid] = qp[tid];
    __syncthreads();

    // scores
    for (int s0 = 0; s0 < len; s0 += 128) {
        int n = min(128, len - s0);
        for (int i = tid; i < n * DD; i += 128)
            ks[(i >> 6) * 65 + (i & 63)] = kb[(size_t)s0 * DD + i];
        __syncthreads();
        if (tid < n) {
            const float* kr = &ks[tid * 65];
            float d0 = 0.f;
#pragma unroll
            for (int c = 0; c < DD; c++) d0 += qs[c] * kr[c];
            sc[s0 + tid] = d0;
        }
        __syncthreads();
    }

    // softmax (two-pass)
    float mx = -1e30f;
    for (int s = tid; s < len; s += 128) mx = fmaxf(mx, sc[s]);
    mx = blockMaxf(mx, red);

    float sum = 0.f;
    for (int s = tid; s < len; s += 128) {
        float e = __expf(sc[s] - mx);
        sc[s] = e;
        sum += e;
    }
    sum = blockSumf(sum, red);   // internal syncthreads makes sc[] visible
    float inv = 1.f / sum;

    // attn @ V : thread = (d, s-parity)
    int d = tid & 63, part = tid >> 6;
    float acc = 0.f;
    for (int s = part; s < len; s += 2)
        acc += sc[s] * vb[(size_t)s * DD + d];
    accs[tid] = acc;
    __syncthreads();
    if (tid < DD) {
        int b = bh >> 4, h = bh & 15;
        attnc[((size_t)b * TT + t) * CC + h * DD + tid] =
            (accs[tid] + accs[tid + 64]) * inv;
    }
}

// ---------------- launch ----------------------------------------------------
extern "C" void kernel_launch(void* const* d_in, const int* in_sizes, int n_in,
                              void* d_out, int out_size)
{
    const float* x   = (const float*)d_in[0];
    const float* Wq  = (const float*)d_in[1];
    const float* Wk  = (const float*)d_in[2];
    const float* Wv  = (const float*)d_in[3];
    const float* Wo  = (const float*)d_in[4];
    const float* bo  = (const float*)d_in[5];
    const float* W1  = (const float*)d_in[6];
    const float* b1  = (const float*)d_in[7];
    const float* W2  = (const float*)d_in[8];
    const float* b2  = (const float*)d_in[9];
    const float* g1  = (const float*)d_in[10];
    const float* be1 = (const float*)d_in[11];
    const float* g2  = (const float*)d_in[12];
    const float* be2 = (const float*)d_in[13];
    float* out = (float*)d_out;

    float *ln, *q, *k, *v, *attnc, *x1, *ff1;
    cudaGetSymbolAddress((void**)&ln,    g_ln);
    cudaGetSymbolAddress((void**)&q,     g_q);
    cudaGetSymbolAddress((void**)&k,     g_k);
    cudaGetSymbolAddress((void**)&v,     g_v);
    cudaGetSymbolAddress((void**)&attnc, g_attnc);
    cudaGetSymbolAddress((void**)&x1,    g_x1);
    cudaGetSymbolAddress((void**)&ff1,   g_ff1);

    // 1. LN1
    ln_kernel<<<NTOK, 256>>>(x, g1, be1, ln);
    // 2. QKV projections (batched over b,h and q/k/v)
    qkv_kernel<<<dim3(TT / 128, 3, BB * HH), 256>>>(ln, Wq, Wk, Wv, q, k, v);
    // 3. causal attention -> concat heads
    attn_kernel<<<dim3(TT, BB * HH), 128>>>(q, k, v, attnc);
    // 4. x1 = x + attnc @ Wo + bo
    sgemm128<1><<<dim3(CC / 128, NTOK / 128), 256>>>(attnc, Wo, x1,
                                                     NTOK, CC, CC, bo, x);
    // 5. LN2
    ln_kernel<<<NTOK, 256>>>(x1, g2, be2, ln);
    // 6. ff1 = relu(ln2 @ W1 + b1)
    sgemm128<2><<<dim3(FFD / 128, NTOK / 128), 256>>>(ln, W1, ff1,
                                                      NTOK, FFD, CC, b1, nullptr);
    // 7. out = x1 + ff1 @ W2 + b2
    sgemm128<1><<<dim3(CC / 128, NTOK / 128), 256>>>(ff1, W2, out,
                                                     NTOK, CC, FFD, b2, x1);
}

// round 4
// speedup vs baseline: 4.5159x; 4.5159x over previous
#include <cuda_runtime.h>
#include <cstdint>

// Problem constants
#define BB 4
#define TT 2048
#define CC 1024
#define HH 16
#define DD 64
#define FFD 4096
#define NTOK (BB*TT)          // 8192

// ---------------- scratch (device globals; no allocation allowed) -----------
__device__ float g_ln   [NTOK * CC];
__device__ float g_q    [BB*HH * TT * DD];
__device__ float g_k    [BB*HH * TT * DD];
__device__ float g_v    [BB*HH * TT * DD];
__device__ float g_attnc[NTOK * CC];
__device__ float g_x1   [NTOK * CC];
__device__ float g_ff1  [NTOK * FFD];
__device__ float g_wqkvT[3*CC * CC];   // [sel*1024 + h*64 + d][c]
__device__ float g_woT  [CC * CC];
__device__ float g_w1T  [FFD * CC];
__device__ float g_w2T  [CC * FFD];

// ---------------- low-level helpers -----------------------------------------
__device__ __forceinline__ uint32_t smem_u32(const void* p) {
    uint32_t a;
    asm("{ .reg .u64 t; cvta.to.shared.u64 t, %1; cvt.u32.u64 %0, t; }"
        : "=r"(a) : "l"(p));
    return a;
}
__device__ __forceinline__ void cp16(uint32_t s, const void* g) {
    asm volatile("cp.async.cg.shared.global [%0], [%1], 16;" :: "r"(s), "l"(g));
}
__device__ __forceinline__ void cpcommit() {
    asm volatile("cp.async.commit_group;" ::: "memory");
}
template <int N>
__device__ __forceinline__ void cpwait() {
    asm volatile("cp.async.wait_group %0;" :: "n"(N) : "memory");
}
// tf32 destination must be a b32 register
__device__ __forceinline__ uint32_t to_tf32(float x) {
    uint32_t r;
    asm("cvt.rna.tf32.f32 %0, %1;" : "=r"(r) : "f"(x));
    return r;
}
// D[4] += A(16x8 tf32) * B(8x8 tf32), m16n8k8
__device__ __forceinline__ void mma8(float* d, uint32_t a0, uint32_t a1,
                                     uint32_t a2, uint32_t a3,
                                     uint32_t b0, uint32_t b1) {
    asm volatile(
        "mma.sync.aligned.m16n8k8.row.col.f32.tf32.tf32.f32 "
        "{%0,%1,%2,%3}, {%4,%5,%6,%7}, {%8,%9}, {%0,%1,%2,%3};"
        : "+f"(d[0]), "+f"(d[1]), "+f"(d[2]), "+f"(d[3])
        : "r"(a0), "r"(a1), "r"(a2), "r"(a3), "r"(b0), "r"(b1));
}

// ================= tf32 mma.sync GEMM ========================================
// C[M,N] = A[M,K] @ BT[N,K]^T. Tile 128x128, BK=32, 3-stage cp.async.
// 256 threads / 8 warps, warp tile 64x32 (4 mtiles x 4 ntiles of m16n8k8).
// EPI: 0 = QKV scatter; 1 = +bias+res; 2 = relu(+bias)
// SPLIT: 1 = 3-term tf32 split (near-fp32 accuracy)
#define GST 3
#define GBK 32
#define GPAD 36
#define GTILE (128*GPAD)                 // floats per stage tile
#define GSMEM_BYTES (2*GST*GTILE*4)      // 110592

template <int NN, int KK, int EPI, int SPLIT>
__global__ void __launch_bounds__(256, 1) mma_gemm(
    const float* __restrict__ A, const float* __restrict__ BT,
    float* __restrict__ O0, float* __restrict__ O1, float* __restrict__ O2,
    const float* __restrict__ bias, const float* __restrict__ res)
{
    extern __shared__ float sm[];
    float* As = sm;
    float* Bs = sm + GST * GTILE;
    uint32_t aS = smem_u32(As), bS = smem_u32(Bs);
    int tid = threadIdx.x, wid = tid >> 5, lane = tid & 31;
    int r = lane >> 2, c = lane & 3;
    int wm = (wid & 1) * 64, wn = (wid >> 1) * 32;
    int row0 = blockIdx.y * 128, col0 = blockIdx.x * 128;
    const float* Ag = A + (size_t)row0 * KK;
    const float* Bg = BT + (size_t)col0 * KK;

    auto loadst = [&](int slot, int kt) {
        uint32_t a_s = aS + slot * GTILE * 4;
        uint32_t b_s = bS + slot * GTILE * 4;
        int k0 = kt * GBK;
#pragma unroll
        for (int i = 0; i < 4; i++) {
            int j = tid + i * 256;          // 0..1023
            int row = j >> 3, cq = j & 7;
            cp16(a_s + (row * GPAD + cq * 4) * 4, Ag + (size_t)row * KK + k0 + cq * 4);
        }
#pragma unroll
        for (int i = 0; i < 4; i++) {
            int j = tid + i * 256;
            int row = j >> 3, cq = j & 7;
            cp16(b_s + (row * GPAD + cq * 4) * 4, Bg + (size_t)row * KK + k0 + cq * 4);
        }
    };

    float acc[4][4][4] = {};
    constexpr int KT = KK / GBK;

    loadst(0, 0); cpcommit();
    loadst(1, 1); cpcommit();

    for (int kt = 0; kt < KT; kt++) {
        if (kt + 2 < KT) loadst((kt + 2) % GST, kt + 2);
        cpcommit();
        cpwait<2>();
        __syncthreads();
        const float* At = As + (kt % GST) * GTILE;
        const float* Bt = Bs + (kt % GST) * GTILE;
#pragma unroll
        for (int ks = 0; ks < 4; ks++) {
            float a[4][4], b[4][2];
#pragma unroll
            for (int mt = 0; mt < 4; mt++) {
                const float* ap = At + (wm + mt * 16 + r) * GPAD + ks * 8 + c;
                a[mt][0] = ap[0];
                a[mt][2] = ap[4];
                a[mt][1] = ap[8 * GPAD];
                a[mt][3] = ap[8 * GPAD + 4];
            }
#pragma unroll
            for (int nt = 0; nt < 4; nt++) {
                const float* bp = Bt + (wn + nt * 8 + r) * GPAD + ks * 8 + c;
                b[nt][0] = bp[0];
                b[nt][1] = bp[4];
            }
            if (SPLIT) {
                uint32_t ah[4][4], al[4][4], bh[4][2], bl[4][2];
#pragma unroll
                for (int mt = 0; mt < 4; mt++)
#pragma unroll
                    for (int j = 0; j < 4; j++) {
                        ah[mt][j] = to_tf32(a[mt][j]);
                        al[mt][j] = to_tf32(a[mt][j] - __uint_as_float(ah[mt][j]));
                    }
#pragma unroll
                for (int nt = 0; nt < 4; nt++)
#pragma unroll
                    for (int j = 0; j < 2; j++) {
                        bh[nt][j] = to_tf32(b[nt][j]);
                        bl[nt][j] = to_tf32(b[nt][j] - __uint_as_float(bh[nt][j]));
                    }
#pragma unroll
                for (int mt = 0; mt < 4; mt++)
#pragma unroll
                    for (int nt = 0; nt < 4; nt++) {
                        mma8(acc[mt][nt], ah[mt][0], ah[mt][1], ah[mt][2], ah[mt][3],
                             bh[nt][0], bh[nt][1]);
                        mma8(acc[mt][nt], al[mt][0], al[mt][1], al[mt][2], al[mt][3],
                             bh[nt][0], bh[nt][1]);
                        mma8(acc[mt][nt], ah[mt][0], ah[mt][1], ah[mt][2], ah[mt][3],
                             bl[nt][0], bl[nt][1]);
                    }
            } else {
                uint32_t au[4][4], bu[4][2];
#pragma unroll
                for (int mt = 0; mt < 4; mt++)
#pragma unroll
                    for (int j = 0; j < 4; j++) au[mt][j] = to_tf32(a[mt][j]);
#pragma unroll
                for (int nt = 0; nt < 4; nt++)
#pragma unroll
                    for (int j = 0; j < 2; j++) bu[nt][j] = to_tf32(b[nt][j]);
#pragma unroll
                for (int mt = 0; mt < 4; mt++)
#pragma unroll
                    for (int nt = 0; nt < 4; nt++)
                        mma8(acc[mt][nt], au[mt][0], au[mt][1], au[mt][2], au[mt][3],
                             bu[nt][0], bu[nt][1]);
            }
        }
        __syncthreads();
    }

    // epilogue: direct float2 stores
#pragma unroll
    for (int mt = 0; mt < 4; mt++) {
        int rg0 = row0 + wm + mt * 16 + r;
#pragma unroll
        for (int nt = 0; nt < 4; nt++) {
            int cg = col0 + wn + nt * 8 + 2 * c;
#pragma unroll
            for (int half = 0; half < 2; half++) {
                int rg = rg0 + half * 8;
                float v0 = acc[mt][nt][half * 2 + 0];
                float v1 = acc[mt][nt][half * 2 + 1];
                if (EPI == 0) {
                    int sel = cg >> 10;
                    int h = (cg >> 6) & 15;
                    int d = cg & 63;
                    int bb = rg >> 11, t = rg & 2047;
                    float* Ob = (sel == 0) ? O0 : (sel == 1) ? O1 : O2;
                    *(float2*)(Ob + ((((size_t)bb * HH + h) * TT + t) << 6) + d) =
                        make_float2(v0, v1);
                } else {
                    size_t off = (size_t)rg * NN + cg;
                    float2 b2 = *(const float2*)(bias + cg);
                    if (EPI == 1) {
                        float2 r2 = *(const float2*)(res + off);
                        v0 += b2.x + r2.x;
                        v1 += b2.y + r2.y;
                    } else {
                        v0 = fmaxf(v0 + b2.x, 0.f);
                        v1 = fmaxf(v1 + b2.y, 0.f);
                    }
                    *(float2*)(O0 + off) = make_float2(v0, v1);
                }
            }
        }
    }
}

// ================= flash attention (tf32 mma, split QK^T) ====================
// Block: 128 q-rows of one (b,h); 8 warps x 16 q-rows; s-tiles of 64.
#define KPAD 68
#define VPAD 72
#define PPAD 68
#define FS_V (2*64*KPAD)
#define FS_P (FS_V + 2*64*VPAD)
#define FSMEM_BYTES ((FS_P + 128*PPAD)*4)   // 106496

__global__ void __launch_bounds__(256, 1) flash_kernel(
    const float* __restrict__ q, const float* __restrict__ k,
    const float* __restrict__ v, float* __restrict__ attnc)
{
    extern __shared__ float sm[];
    float* Ks = sm;
    float* Vs = sm + FS_V;
    float* Ps = sm + FS_P;
    uint32_t kBase = smem_u32(Ks), vBase = smem_u32(Vs);
    int tid = threadIdx.x, wid = tid >> 5, lane = tid & 31;
    int r = lane >> 2, c = lane & 3;
    int qt = (int)gridDim.x - 1 - (int)blockIdx.x;   // longest blocks first
    int bh = blockIdx.y;
    int t0 = qt * 128;
    int wq = wid * 16;
    const float* qb = q + (size_t)bh * TT * DD;
    const float* kb = k + (size_t)bh * TT * DD;
    const float* vb = v + (size_t)bh * TT * DD;

    // load Q tile into Ps (fp32), then register fragments
#pragma unroll
    for (int i = 0; i < 8; i++) {
        int j = tid + i * 256;
        int row = j >> 4, c4 = j & 15;
        *(float4*)(Ps + row * PPAD + c4 * 4) =
            *(const float4*)(qb + (size_t)(t0 + row) * DD + c4 * 4);
    }
    __syncthreads();
    // pre-split Q fragments (hi/lo tf32)
    uint32_t qh[8][4], ql[8][4];
#pragma unroll
    for (int ks = 0; ks < 8; ks++) {
        const float* qp = Ps + (wq + r) * PPAD + ks * 8 + c;
        float f0 = qp[0], f2 = qp[4];
        float f1 = qp[8 * PPAD], f3 = qp[8 * PPAD + 4];
        qh[ks][0] = to_tf32(f0); ql[ks][0] = to_tf32(f0 - __uint_as_float(qh[ks][0]));
        qh[ks][1] = to_tf32(f1); ql[ks][1] = to_tf32(f1 - __uint_as_float(qh[ks][1]));
        qh[ks][2] = to_tf32(f2); ql[ks][2] = to_tf32(f2 - __uint_as_float(qh[ks][2]));
        qh[ks][3] = to_tf32(f3); ql[ks][3] = to_tf32(f3 - __uint_as_float(qh[ks][3]));
    }
    __syncthreads();                 // Ps now reused for P

    auto loadkv = [&](int buf, int it) {
        int s0 = it * 64;
        uint32_t kS = kBase + buf * 64 * KPAD * 4;
        uint32_t vS = vBase + buf * 64 * VPAD * 4;
#pragma unroll
        for (int i = 0; i < 4; i++) {
            int j = tid + i * 256;
            int row = j >> 4, cq = j & 15;
            cp16(kS + (row * KPAD + cq * 4) * 4, kb + (size_t)(s0 + row) * DD + cq * 4);
        }
#pragma unroll
        for (int i = 0; i < 4; i++) {
            int j = tid + i * 256;
            int row = j >> 4, cq = j & 15;
            cp16(vS + (row * VPAD + cq * 4) * 4, vb + (size_t)(s0 + row) * DD + cq * 4);
        }
    };

    int nst = 2 * qt + 2;
    loadkv(0, 0); cpcommit();

    float m0 = -1e30f, m1 = -1e30f, l0 = 0.f, l1 = 0.f;
    float O[8][4] = {};
    float* Pw = Ps + wq * PPAD;

    for (int it = 0; it < nst; it++) {
        if (it + 1 < nst) loadkv((it + 1) & 1, it + 1);
        cpcommit();
        cpwait<1>();
        __syncthreads();
        const float* Kt = Ks + (it & 1) * 64 * KPAD;
        const float* Vt = Vs + (it & 1) * 64 * VPAD;

        // ---- S = Q K^T (split tf32, 3 terms) ----
        float S[8][4] = {};
#pragma unroll
        for (int ks = 0; ks < 8; ks++) {
#pragma unroll
            for (int nt = 0; nt < 8; nt++) {
                const float* kp = Kt + (nt * 8 + r) * KPAD + ks * 8 + c;
                float kb0 = kp[0], kb1 = kp[4];
                uint32_t kh0 = to_tf32(kb0), kh1 = to_tf32(kb1);
                uint32_t kl0 = to_tf32(kb0 - __uint_as_float(kh0));
                uint32_t kl1 = to_tf32(kb1 - __uint_as_float(kh1));
                mma8(S[nt], qh[ks][0], qh[ks][1], qh[ks][2], qh[ks][3], kh0, kh1);
                mma8(S[nt], ql[ks][0], ql[ks][1], ql[ks][2], ql[ks][3], kh0, kh1);
                mma8(S[nt], qh[ks][0], qh[ks][1], qh[ks][2], qh[ks][3], kl0, kl1);
            }
        }

        // ---- causal mask ----
        int s0 = it * 64;
        if (s0 + 63 > t0 + wq) {
#pragma unroll
            for (int nt = 0; nt < 8; nt++)
#pragma unroll
                for (int jj = 0; jj < 4; jj++) {
                    int scol = s0 + nt * 8 + 2 * c + (jj & 1);
                    int trow = t0 + wq + r + ((jj >> 1) << 3);
                    if (scol > trow) S[nt][jj] = -1e30f;
                }
        }

        // ---- online softmax ----
        float mx0 = -1e30f, mx1 = -1e30f;
#pragma unroll
        for (int nt = 0; nt < 8; nt++) {
            mx0 = fmaxf(mx0, fmaxf(S[nt][0], S[nt][1]));
            mx1 = fmaxf(mx1, fmaxf(S[nt][2], S[nt][3]));
        }
        mx0 = fmaxf(mx0, __shfl_xor_sync(0xffffffffu, mx0, 1));
        mx0 = fmaxf(mx0, __shfl_xor_sync(0xffffffffu, mx0, 2));
        mx1 = fmaxf(mx1, __shfl_xor_sync(0xffffffffu, mx1, 1));
        mx1 = fmaxf(mx1, __shfl_xor_sync(0xffffffffu, mx1, 2));
        float nm0 = fmaxf(m0, mx0), nm1 = fmaxf(m1, mx1);
        float al0 = __expf(m0 - nm0), al1 = __expf(m1 - nm1);
        m0 = nm0; m1 = nm1;
        float su0 = 0.f, su1 = 0.f;
#pragma unroll
        for (int nt = 0; nt < 8; nt++) {
            S[nt][0] = __expf(S[nt][0] - nm0);
            S[nt][1] = __expf(S[nt][1] - nm0);
            S[nt][2] = __expf(S[nt][2] - nm1);
            S[nt][3] = __expf(S[nt][3] - nm1);
            su0 += S[nt][0] + S[nt][1];
            su1 += S[nt][2] + S[nt][3];
        }
        su0 += __shfl_xor_sync(0xffffffffu, su0, 1);
        su0 += __shfl_xor_sync(0xffffffffu, su0, 2);
        su1 += __shfl_xor_sync(0xffffffffu, su1, 1);
        su1 += __shfl_xor_sync(0xffffffffu, su1, 2);
        l0 = l0 * al0 + su0;
        l1 = l1 * al1 + su1;
#pragma unroll
        for (int nt = 0; nt < 8; nt++) {
            O[nt][0] *= al0; O[nt][1] *= al0;
            O[nt][2] *= al1; O[nt][3] *= al1;
        }

        // ---- P to warp-private SMEM (tf32-rounded) ----
#pragma unroll
        for (int nt = 0; nt < 8; nt++) {
            *(float2*)(Pw + r * PPAD + nt * 8 + 2 * c) =
                make_float2(__uint_as_float(to_tf32(S[nt][0])),
                            __uint_as_float(to_tf32(S[nt][1])));
            *(float2*)(Pw + (r + 8) * PPAD + nt * 8 + 2 * c) =
                make_float2(__uint_as_float(to_tf32(S[nt][2])),
                            __uint_as_float(to_tf32(S[nt][3])));
        }
        __syncwarp();

        // ---- O += P V ----
#pragma unroll
        for (int ks = 0; ks < 8; ks++) {
            const float* pp = Pw + r * PPAD + ks * 8 + c;
            uint32_t a0 = __float_as_uint(pp[0]);
            uint32_t a2 = __float_as_uint(pp[4]);
            uint32_t a1 = __float_as_uint(pp[8 * PPAD]);
            uint32_t a3 = __float_as_uint(pp[8 * PPAD + 4]);
#pragma unroll
            for (int nt = 0; nt < 8; nt++) {
                const float* vp = Vt + (ks * 8 + c) * VPAD + nt * 8 + r;
                uint32_t b0 = to_tf32(vp[0]);
                uint32_t b1 = to_tf32(vp[4 * VPAD]);
                mma8(O[nt], a0, a1, a2, a3, b0, b1);
            }
        }
        __syncthreads();    // protect K/V buffer reuse next iteration
    }

    // ---- normalize + write ----
    float i0 = 1.f / l0, i1 = 1.f / l1;
    int b = bh >> 4, h = bh & 15;
    int tr0 = t0 + wq + r;
#pragma unroll
    for (int nt = 0; nt < 8; nt++) {
        int col = h * 64 + nt * 8 + 2 * c;
        *(float2*)(attnc + (size_t)(b * TT + tr0) * CC + col) =
            make_float2(O[nt][0] * i0, O[nt][1] * i0);
        *(float2*)(attnc + (size_t)(b * TT + tr0 + 8) * CC + col) =
            make_float2(O[nt][2] * i1, O[nt][3] * i1);
    }
}

// ---------------- tiled transpose: out[Cc,R] = in[R,Cc]^T, batched ----------
__global__ void transpose_kernel(const float* __restrict__ in, float* __restrict__ out,
                                 int R, int Cc, size_t in_bs, size_t out_bs)
{
    __shared__ float tile[32][33];
    in  += (size_t)blockIdx.z * in_bs;
    out += (size_t)blockIdx.z * out_bs;
    int c0 = blockIdx.x * 32, r0 = blockIdx.y * 32;
    int x = threadIdx.x, y = threadIdx.y;
#pragma unroll
    for (int i = 0; i < 32; i += 8)
        tile[y + i][x] = in[(size_t)(r0 + y + i) * Cc + c0 + x];
    __syncthreads();
#pragma unroll
    for (int i = 0; i < 32; i += 8)
        out[(size_t)(c0 + y + i) * R + r0 + x] = tile[x][y + i];
}

// ---------------- block reduction + LayerNorm --------------------------------
__device__ __forceinline__ float blockSumf(float v, float* red) {
    int lane = threadIdx.x & 31, w = threadIdx.x >> 5, nw = blockDim.x >> 5;
    __syncthreads();
#pragma unroll
    for (int o = 16; o > 0; o >>= 1) v += __shfl_xor_sync(0xffffffffu, v, o);
    if (lane == 0) red[w] = v;
    __syncthreads();
    if (w == 0) {
        float t = (lane < nw) ? red[lane] : 0.f;
#pragma unroll
        for (int o = 16; o > 0; o >>= 1) t += __shfl_xor_sync(0xffffffffu, t, o);
        if (lane == 0) red[0] = t;
    }
    __syncthreads();
    return red[0];
}

__global__ void __launch_bounds__(256) ln_kernel(
    const float* __restrict__ x, const float* __restrict__ g,
    const float* __restrict__ be, float* __restrict__ out)
{
    __shared__ float red[8];
    size_t row = blockIdx.x;
    const float* xr = x + row * CC;
    float* orow = out + row * CC;
    float v[4], s = 0.f, s2 = 0.f;
#pragma unroll
    for (int i = 0; i < 4; i++) {
        int idx = threadIdx.x + i * 256;
        v[i] = xr[idx];
        s += v[i];
        s2 += v[i] * v[i];
    }
    s  = blockSumf(s, red);
    s2 = blockSumf(s2, red);
    float mu  = s * (1.f / CC);
    float var = s2 * (1.f / CC) - mu * mu;
    float rstd = rsqrtf(var + 1e-5f);
#pragma unroll
    for (int i = 0; i < 4; i++) {
        int idx = threadIdx.x + i * 256;
        orow[idx] = (v[i] - mu) * rstd * g[idx] + be[idx];
    }
}

// ---------------- launch ----------------------------------------------------
extern "C" void kernel_launch(void* const* d_in, const int* in_sizes, int n_in,
                              void* d_out, int out_size)
{
    const float* x   = (const float*)d_in[0];
    const float* Wq  = (const float*)d_in[1];
    const float* Wk  = (const float*)d_in[2];
    const float* Wv  = (const float*)d_in[3];
    const float* Wo  = (const float*)d_in[4];
    const float* bo  = (const float*)d_in[5];
    const float* W1  = (const float*)d_in[6];
    const float* b1  = (const float*)d_in[7];
    const float* W2  = (const float*)d_in[8];
    const float* b2  = (const float*)d_in[9];
    const float* g1  = (const float*)d_in[10];
    const float* be1 = (const float*)d_in[11];
    const float* g2  = (const float*)d_in[12];
    const float* be2 = (const float*)d_in[13];
    float* out = (float*)d_out;

    float *ln, *q, *k, *v, *attnc, *x1, *ff1, *wqkvT, *woT, *w1T, *w2T;
    cudaGetSymbolAddress((void**)&ln,    g_ln);
    cudaGetSymbolAddress((void**)&q,     g_q);
    cudaGetSymbolAddress((void**)&k,     g_k);
    cudaGetSymbolAddress((void**)&v,     g_v);
    cudaGetSymbolAddress((void**)&attnc, g_attnc);
    cudaGetSymbolAddress((void**)&x1,    g_x1);
    cudaGetSymbolAddress((void**)&ff1,   g_ff1);
    cudaGetSymbolAddress((void**)&wqkvT, g_wqkvT);
    cudaGetSymbolAddress((void**)&woT,   g_woT);
    cudaGetSymbolAddress((void**)&w1T,   g_w1T);
    cudaGetSymbolAddress((void**)&w2T,   g_w2T);

    cudaFuncSetAttribute(mma_gemm<3072,1024,0,1>, cudaFuncAttributeMaxDynamicSharedMemorySize, GSMEM_BYTES);
    cudaFuncSetAttribute(mma_gemm<1024,1024,1,0>, cudaFuncAttributeMaxDynamicSharedMemorySize, GSMEM_BYTES);
    cudaFuncSetAttribute(mma_gemm<4096,1024,2,0>, cudaFuncAttributeMaxDynamicSharedMemorySize, GSMEM_BYTES);
    cudaFuncSetAttribute(mma_gemm<1024,4096,1,0>, cudaFuncAttributeMaxDynamicSharedMemorySize, GSMEM_BYTES);
    cudaFuncSetAttribute(flash_kernel, cudaFuncAttributeMaxDynamicSharedMemorySize, FSMEM_BYTES);

    dim3 tb(32, 8);
    transpose_kernel<<<dim3(32, 32, 1),  tb>>>(Wo, woT, CC, CC, 0, 0);
    transpose_kernel<<<dim3(128, 32, 1), tb>>>(W1, w1T, CC, FFD, 0, 0);
    transpose_kernel<<<dim3(32, 128, 1), tb>>>(W2, w2T, FFD, CC, 0, 0);
    transpose_kernel<<<dim3(2, 32, 16),  tb>>>(Wq, wqkvT,           CC, DD, (size_t)CC*DD, (size_t)DD*CC);
    transpose_kernel<<<dim3(2, 32, 16),  tb>>>(Wk, wqkvT + CC*CC,   CC, DD, (size_t)CC*DD, (size_t)DD*CC);
    transpose_kernel<<<dim3(2, 32, 16),  tb>>>(Wv, wqkvT + 2*CC*CC, CC, DD, (size_t)CC*DD, (size_t)DD*CC);

    // 1. LN1
    ln_kernel<<<NTOK, 256>>>(x, g1, be1, ln);
    // 2. fused QKV (split tf32 for accuracy), scatter epilogue
    mma_gemm<3072,1024,0,1><<<dim3(24, 64), 256, GSMEM_BYTES>>>(
        ln, wqkvT, q, k, v, nullptr, nullptr);
    // 3. flash attention -> concat heads
    flash_kernel<<<dim3(16, 64), 256, FSMEM_BYTES>>>(q, k, v, attnc);
    // 4. x1 = x + attnc @ Wo + bo
    mma_gemm<1024,1024,1,0><<<dim3(8, 64), 256, GSMEM_BYTES>>>(
        attnc, woT, x1, nullptr, nullptr, bo, x);
    // 5. LN2
    ln_kernel<<<NTOK, 256>>>(x1, g2, be2, ln);
    // 6. ff1 = relu(ln2 @ W1 + b1)
    mma_gemm<4096,1024,2,0><<<dim3(32, 64), 256, GSMEM_BYTES>>>(
        ln, w1T, ff1, nullptr, nullptr, b1, nullptr);
    // 7. out = x1 + ff1 @ W2 + b2
    mma_gemm<1024,4096,1,0><<<dim3(8, 64), 256, GSMEM_BYTES>>>(
        ff1, w2T, out, nullptr, nullptr, b2, x1);
}

// round 5
// speedup vs baseline: 5.6487x; 1.2509x over previous
#include <cuda_runtime.h>
#include <cuda_bf16.h>
#include <cstdint>

// Problem constants
#define BB 4
#define TT 2048
#define CC 1024
#define HH 16
#define DD 64
#define FFD 4096
#define NTOK (BB*TT)          // 8192

// ---------------- scratch (device globals; no allocation allowed) -----------
__device__ float         g_lnF [NTOK * CC];          // LN2 output fp32
__device__ __nv_bfloat16 g_lnH [NTOK * CC];          // LN1 output hi
__device__ __nv_bfloat16 g_lnL [NTOK * CC];          // LN1 output lo
__device__ float         g_q   [BB*HH * TT * DD];
__device__ __nv_bfloat16 g_kH  [BB*HH * TT * DD];
__device__ __nv_bfloat16 g_kL  [BB*HH * TT * DD];
__device__ float         g_v   [BB*HH * TT * DD];
__device__ float         g_attnc[NTOK * CC];
__device__ float         g_x1  [NTOK * CC];
__device__ float         g_ff1 [NTOK * FFD];
__device__ __nv_bfloat16 g_wqkvTH[3*CC * CC];        // [sel*1024 + h*64 + d][c]
__device__ __nv_bfloat16 g_wqkvTL[3*CC * CC];
__device__ float         g_woT [CC * CC];
__device__ float         g_w1T [FFD * CC];
__device__ float         g_w2T [CC * FFD];

// ---------------- low-level helpers -----------------------------------------
__device__ __forceinline__ uint32_t smem_u32(const void* p) {
    uint32_t a;
    asm("{ .reg .u64 t; cvta.to.shared.u64 t, %1; cvt.u32.u64 %0, t; }"
        : "=r"(a) : "l"(p));
    return a;
}
__device__ __forceinline__ void cp16(uint32_t s, const void* g) {
    asm volatile("cp.async.cg.shared.global [%0], [%1], 16;" :: "r"(s), "l"(g));
}
__device__ __forceinline__ void cpcommit() {
    asm volatile("cp.async.commit_group;" ::: "memory");
}
template <int N>
__device__ __forceinline__ void cpwait() {
    asm volatile("cp.async.wait_group %0;" :: "n"(N) : "memory");
}
__device__ __forceinline__ uint32_t to_tf32(float x) {
    uint32_t r;
    asm("cvt.rna.tf32.f32 %0, %1;" : "=r"(r) : "f"(x));
    return r;
}
// D[4] += A(16x8 tf32) * B(8x8 tf32), m16n8k8
__device__ __forceinline__ void mma8(float* d, uint32_t a0, uint32_t a1,
                                     uint32_t a2, uint32_t a3,
                                     uint32_t b0, uint32_t b1) {
    asm volatile(
        "mma.sync.aligned.m16n8k8.row.col.f32.tf32.tf32.f32 "
        "{%0,%1,%2,%3}, {%4,%5,%6,%7}, {%8,%9}, {%0,%1,%2,%3};"
        : "+f"(d[0]), "+f"(d[1]), "+f"(d[2]), "+f"(d[3])
        : "r"(a0), "r"(a1), "r"(a2), "r"(a3), "r"(b0), "r"(b1));
}
// D[4] += A(16x16 bf16) * B(16x8 bf16), m16n8k16
__device__ __forceinline__ void mma16(float* d, uint32_t a0, uint32_t a1,
                                      uint32_t a2, uint32_t a3,
                                      uint32_t b0, uint32_t b1) {
    asm volatile(
        "mma.sync.aligned.m16n8k16.row.col.f32.bf16.bf16.f32 "
        "{%0,%1,%2,%3}, {%4,%5,%6,%7}, {%8,%9}, {%0,%1,%2,%3};"
        : "+f"(d[0]), "+f"(d[1]), "+f"(d[2]), "+f"(d[3])
        : "r"(a0), "r"(a1), "r"(a2), "r"(a3), "r"(b0), "r"(b1));
}
__device__ __forceinline__ uint32_t packbf(float x, float y) {
    __nv_bfloat162 t = __floats2bfloat162_rn(x, y);
    return *reinterpret_cast<uint32_t*>(&t);
}
__device__ __forceinline__ void splitbf(float x, float y, uint32_t& hp, uint32_t& lp) {
    float hx = __bfloat162float(__float2bfloat16(x));
    float hy = __bfloat162float(__float2bfloat16(y));
    hp = packbf(hx, hy);
    lp = packbf(x - hx, y - hy);
}

// ================= QKV GEMM: bf16x3, tile 128x128, BK=32, 3 stages ===========
// A = lnH/lnL [8192,1024], B = wqkvTH/L [3072,1024]; epilogue scatters q (fp32),
// k (bf16 hi/lo), v (fp32) into per-head layout.
#define QST 3
#define QPADU 20
#define QTILEU (128*QPADU)                 // u32 per array per stage
#define QSMEM_BYTES (4*QST*QTILEU*4)       // 122880

__global__ void __launch_bounds__(256, 1) qkv_gemm(
    const __nv_bfloat16* __restrict__ AH, const __nv_bfloat16* __restrict__ AL,
    const __nv_bfloat16* __restrict__ BH, const __nv_bfloat16* __restrict__ BL,
    float* __restrict__ qo, uint32_t* __restrict__ kHo,
    uint32_t* __restrict__ kLo, float* __restrict__ vo)
{
    extern __shared__ uint32_t smq[];
    uint32_t* AHs = smq;
    uint32_t* ALs = smq + QST * QTILEU;
    uint32_t* BHs = smq + 2 * QST * QTILEU;
    uint32_t* BLs = smq + 3 * QST * QTILEU;
    uint32_t aH = smem_u32(AHs), aL = smem_u32(ALs);
    uint32_t bH = smem_u32(BHs), bL = smem_u32(BLs);
    int tid = threadIdx.x, wid = tid >> 5, lane = tid & 31;
    int r = lane >> 2, c = lane & 3;
    int wm = (wid & 1) * 64, wn = (wid >> 1) * 32;
    int row0 = blockIdx.y * 128, col0 = blockIdx.x * 128;

    auto loadst = [&](int slot, int kt) {
        int k0 = kt * 32;
#pragma unroll
        for (int i = 0; i < 2; i++) {
            int j = tid + i * 256;       // 0..511
            int row = j >> 2, ch = j & 3;
            uint32_t doff = (uint32_t)(slot * QTILEU + row * QPADU + ch * 4) * 4;
            size_t sa = (size_t)(row0 + row) * CC + k0 + ch * 8;
            size_t sb = (size_t)(col0 + row) * CC + k0 + ch * 8;
            cp16(aH + doff, AH + sa);
            cp16(aL + doff, AL + sa);
            cp16(bH + doff, BH + sb);
            cp16(bL + doff, BL + sb);
        }
    };

    float acc[4][4][4] = {};
    loadst(0, 0); cpcommit();
    loadst(1, 1); cpcommit();

    for (int kt = 0; kt < 32; kt++) {
        if (kt + 2 < 32) loadst((kt + 2) % QST, kt + 2);
        cpcommit();
        cpwait<2>();
        __syncthreads();
        const uint32_t* AHt = AHs + (kt % QST) * QTILEU;
        const uint32_t* ALt = ALs + (kt % QST) * QTILEU;
        const uint32_t* BHt = BHs + (kt % QST) * QTILEU;
        const uint32_t* BLt = BLs + (kt % QST) * QTILEU;
#pragma unroll
        for (int s = 0; s < 2; s++) {
            int pb = s * 8;
            uint32_t ah[4][4], al[4][4], bh[4][2], bl[4][2];
#pragma unroll
            for (int mt = 0; mt < 4; mt++) {
                int rr = wm + mt * 16;
                ah[mt][0] = AHt[(rr + r) * QPADU + pb + c];
                ah[mt][1] = AHt[(rr + r + 8) * QPADU + pb + c];
                ah[mt][2] = AHt[(rr + r) * QPADU + pb + c + 4];
                ah[mt][3] = AHt[(rr + r + 8) * QPADU + pb + c + 4];
                al[mt][0] = ALt[(rr + r) * QPADU + pb + c];
                al[mt][1] = ALt[(rr + r + 8) * QPADU + pb + c];
                al[mt][2] = ALt[(rr + r) * QPADU + pb + c + 4];
                al[mt][3] = ALt[(rr + r + 8) * QPADU + pb + c + 4];
            }
#pragma unroll
            for (int nt = 0; nt < 4; nt++) {
                int cc_ = wn + nt * 8 + r;
                bh[nt][0] = BHt[cc_ * QPADU + pb + c];
                bh[nt][1] = BHt[cc_ * QPADU + pb + c + 4];
                bl[nt][0] = BLt[cc_ * QPADU + pb + c];
                bl[nt][1] = BLt[cc_ * QPADU + pb + c + 4];
            }
#pragma unroll
            for (int mt = 0; mt < 4; mt++)
#pragma unroll
                for (int nt = 0; nt < 4; nt++) {
                    mma16(acc[mt][nt], ah[mt][0], ah[mt][1], ah[mt][2], ah[mt][3],
                          bh[nt][0], bh[nt][1]);
                    mma16(acc[mt][nt], al[mt][0], al[mt][1], al[mt][2], al[mt][3],
                          bh[nt][0], bh[nt][1]);
                    mma16(acc[mt][nt], ah[mt][0], ah[mt][1], ah[mt][2], ah[mt][3],
                          bl[nt][0], bl[nt][1]);
                }
        }
        __syncthreads();
    }

    // epilogue: scatter q/k/v per head
#pragma unroll
    for (int mt = 0; mt < 4; mt++) {
        int rg0 = row0 + wm + mt * 16 + r;
#pragma unroll
        for (int nt = 0; nt < 4; nt++) {
            int cg = col0 + wn + nt * 8 + 2 * c;
            int sel = cg >> 10;
            int h = (cg >> 6) & 15;
            int d = cg & 63;
#pragma unroll
            for (int half = 0; half < 2; half++) {
                int rg = rg0 + half * 8;
                int bb = rg >> 11, t = rg & 2047;
                float v0 = acc[mt][nt][half * 2 + 0];
                float v1 = acc[mt][nt][half * 2 + 1];
                size_t ofs = (((size_t)(bb * HH + h) * TT + t) << 6) + d;
                if (sel == 0) {
                    *(float2*)(qo + ofs) = make_float2(v0, v1);
                } else if (sel == 2) {
                    *(float2*)(vo + ofs) = make_float2(v0, v1);
                } else {
                    uint32_t hp, lp;
                    splitbf(v0, v1, hp, lp);
                    kHo[ofs >> 1] = hp;
                    kLo[ofs >> 1] = lp;
                }
            }
        }
    }
}

// ================= tf32 mma.sync GEMM (Wo, W1, W2) ===========================
#define GST 3
#define GBK 32
#define GPAD 36
#define GTILE (128*GPAD)
#define GSMEM_BYTES (2*GST*GTILE*4)      // 110592

template <int NN, int KK, int EPI>      // EPI: 1 = +bias+res, 2 = relu(+bias)
__global__ void __launch_bounds__(256, 1) mma_gemm(
    const float* __restrict__ A, const float* __restrict__ BT,
    float* __restrict__ O,
    const float* __restrict__ bias, const float* __restrict__ res)
{
    extern __shared__ float sm[];
    float* As = sm;
    float* Bs = sm + GST * GTILE;
    uint32_t aS = smem_u32(As), bS = smem_u32(Bs);
    int tid = threadIdx.x, wid = tid >> 5, lane = tid & 31;
    int r = lane >> 2, c = lane & 3;
    int wm = (wid & 1) * 64, wn = (wid >> 1) * 32;
    int row0 = blockIdx.y * 128, col0 = blockIdx.x * 128;
    const float* Ag = A + (size_t)row0 * KK;
    const float* Bg = BT + (size_t)col0 * KK;

    auto loadst = [&](int slot, int kt) {
        uint32_t a_s = aS + slot * GTILE * 4;
        uint32_t b_s = bS + slot * GTILE * 4;
        int k0 = kt * GBK;
#pragma unroll
        for (int i = 0; i < 4; i++) {
            int j = tid + i * 256;
            int row = j >> 3, cq = j & 7;
            cp16(a_s + (row * GPAD + cq * 4) * 4, Ag + (size_t)row * KK + k0 + cq * 4);
        }
#pragma unroll
        for (int i = 0; i < 4; i++) {
            int j = tid + i * 256;
            int row = j >> 3, cq = j & 7;
            cp16(b_s + (row * GPAD + cq * 4) * 4, Bg + (size_t)row * KK + k0 + cq * 4);
        }
    };

    float acc[4][4][4] = {};
    constexpr int KT = KK / GBK;

    loadst(0, 0); cpcommit();
    loadst(1, 1); cpcommit();

    for (int kt = 0; kt < KT; kt++) {
        if (kt + 2 < KT) loadst((kt + 2) % GST, kt + 2);
        cpcommit();
        cpwait<2>();
        __syncthreads();
        const float* At = As + (kt % GST) * GTILE;
        const float* Bt = Bs + (kt % GST) * GTILE;
#pragma unroll
        for (int ks = 0; ks < 4; ks++) {
            uint32_t a[4][4], b[4][2];
#pragma unroll
            for (int mt = 0; mt < 4; mt++) {
                const float* ap = At + (wm + mt * 16 + r) * GPAD + ks * 8 + c;
                a[mt][0] = to_tf32(ap[0]);
                a[mt][2] = to_tf32(ap[4]);
                a[mt][1] = to_tf32(ap[8 * GPAD]);
                a[mt][3] = to_tf32(ap[8 * GPAD + 4]);
            }
#pragma unroll
            for (int nt = 0; nt < 4; nt++) {
                const float* bp = Bt + (wn + nt * 8 + r) * GPAD + ks * 8 + c;
                b[nt][0] = to_tf32(bp[0]);
                b[nt][1] = to_tf32(bp[4]);
            }
#pragma unroll
            for (int mt = 0; mt < 4; mt++)
#pragma unroll
                for (int nt = 0; nt < 4; nt++)
                    mma8(acc[mt][nt], a[mt][0], a[mt][1], a[mt][2], a[mt][3],
                         b[nt][0], b[nt][1]);
        }
        __syncthreads();
    }

#pragma unroll
    for (int mt = 0; mt < 4; mt++) {
        int rg0 = row0 + wm + mt * 16 + r;
#pragma unroll
        for (int nt = 0; nt < 4; nt++) {
            int cg = col0 + wn + nt * 8 + 2 * c;
#pragma unroll
            for (int half = 0; half < 2; half++) {
                int rg = rg0 + half * 8;
                float v0 = acc[mt][nt][half * 2 + 0];
                float v1 = acc[mt][nt][half * 2 + 1];
                size_t off = (size_t)rg * NN + cg;
                float2 b2 = *(const float2*)(bias + cg);
                if (EPI == 1) {
                    float2 r2 = *(const float2*)(res + off);
                    v0 += b2.x + r2.x;
                    v1 += b2.y + r2.y;
                } else {
                    v0 = fmaxf(v0 + b2.x, 0.f);
                    v1 = fmaxf(v1 + b2.y, 0.f);
                }
                *(float2*)(O + off) = make_float2(v0, v1);
            }
        }
    }
}

// ================= flash attention: bf16x3 QK^T, tf32 PV =====================
#define KPADU 36                 // u32 stride of K pair tiles
#define VPAD 72
#define PPAD 68
#define F_KH 0
#define F_KL 18432
#define F_V  36864
#define F_PS 73728
#define FSMEM_BYTES 108544

__global__ void __launch_bounds__(256, 1) flash_kernel(
    const float* __restrict__ q, const __nv_bfloat16* __restrict__ kH,
    const __nv_bfloat16* __restrict__ kL,
    const float* __restrict__ v, float* __restrict__ attnc)
{
    extern __shared__ char smc[];
    uint32_t base = smem_u32(smc);
    uint32_t* KHs = (uint32_t*)(smc + F_KH);
    uint32_t* KLs = (uint32_t*)(smc + F_KL);
    float* Vs = (float*)(smc + F_V);
    float* Ps = (float*)(smc + F_PS);

    int tid = threadIdx.x, wid = tid >> 5, lane = tid & 31;
    int r = lane >> 2, c = lane & 3;
    int qt = (int)gridDim.x - 1 - (int)blockIdx.x;   // longest blocks first
    int bh = blockIdx.y;
    int t0 = qt * 128;
    int wq = wid * 16;
    const float* qb = q + (size_t)bh * TT * DD;
    const __nv_bfloat16* kHb = kH + (size_t)bh * TT * DD;
    const __nv_bfloat16* kLb = kL + (size_t)bh * TT * DD;
    const float* vb = v + (size_t)bh * TT * DD;

    // load Q tile into Ps (fp32)
#pragma unroll
    for (int i = 0; i < 8; i++) {
        int j = tid + i * 256;
        int row = j >> 4, c4 = j & 15;
        *(float4*)(Ps + row * PPAD + c4 * 4) =
            *(const float4*)(qb + (size_t)(t0 + row) * DD + c4 * 4);
    }
    __syncthreads();
    // pre-split Q fragments: packed bf16 hi/lo pairs per k16 step
    uint32_t qhp[4][4], qlp[4][4];
#pragma unroll
    for (int s = 0; s < 4; s++) {
        const float* q0 = Ps + (wq + r) * PPAD + 16 * s;
        const float* q1 = Ps + (wq + r + 8) * PPAD + 16 * s;
        splitbf(q0[2 * c],     q0[2 * c + 1], qhp[s][0], qlp[s][0]);
        splitbf(q1[2 * c],     q1[2 * c + 1], qhp[s][1], qlp[s][1]);
        splitbf(q0[2 * c + 8], q0[2 * c + 9], qhp[s][2], qlp[s][2]);
        splitbf(q1[2 * c + 8], q1[2 * c + 9], qhp[s][3], qlp[s][3]);
    }
    __syncthreads();                 // Ps now reused for P

    auto loadkv = [&](int buf, int it) {
        int s0 = it * 64;
        uint32_t kh = base + F_KH + buf * 9216;
        uint32_t kl = base + F_KL + buf * 9216;
        uint32_t vs = base + F_V + buf * 64 * VPAD * 4;
#pragma unroll
        for (int i = 0; i < 2; i++) {
            int j = tid + i * 256;       // 0..511
            int row = j >> 3, ch = j & 7;
            uint32_t doff = (uint32_t)(row * KPADU + ch * 4) * 4;
            size_t src = (size_t)(s0 + row) * DD + ch * 8;
            cp16(kh + doff, kHb + src);
            cp16(kl + doff, kLb + src);
        }
#pragma unroll
        for (int i = 0; i < 4; i++) {
            int j = tid + i * 256;       // 0..1023
            int row = j >> 4, ch = j & 15;
            cp16(vs + (uint32_t)(row * VPAD + ch * 4) * 4,
                 vb + (size_t)(s0 + row) * DD + ch * 4);
        }
    };

    int nst = 2 * qt + 2;
    loadkv(0, 0); cpcommit();

    float m0 = -1e30f, m1 = -1e30f, l0 = 0.f, l1 = 0.f;
    float O[8][4] = {};
    float* Pw = Ps + wq * PPAD;

    for (int it = 0; it < nst; it++) {
        if (it + 1 < nst) loadkv((it + 1) & 1, it + 1);
        cpcommit();
        cpwait<1>();
        __syncthreads();
        const uint32_t* KHt = KHs + (it & 1) * 2304;   // 9216B / 4
        const uint32_t* KLt = KLs + (it & 1) * 2304;
        const float* Vt = Vs + (it & 1) * 64 * VPAD;

        // ---- S = Q K^T (bf16x3) ----
        float S[8][4] = {};
#pragma unroll
        for (int s = 0; s < 4; s++) {
#pragma unroll
            for (int nt = 0; nt < 8; nt++) {
                const uint32_t* kp = KHt + (nt * 8 + r) * KPADU + s * 8 + c;
                const uint32_t* lp = KLt + (nt * 8 + r) * KPADU + s * 8 + c;
                uint32_t b0 = kp[0], b1 = kp[4];
                uint32_t l0r = lp[0], l1r = lp[4];
                mma16(S[nt], qhp[s][0], qhp[s][1], qhp[s][2], qhp[s][3], b0, b1);
                mma16(S[nt], qlp[s][0], qlp[s][1], qlp[s][2], qlp[s][3], b0, b1);
                mma16(S[nt], qhp[s][0], qhp[s][1], qhp[s][2], qhp[s][3], l0r, l1r);
            }
        }

        // ---- causal mask ----
        int s0 = it * 64;
        if (s0 + 63 > t0 + wq) {
#pragma unroll
            for (int nt = 0; nt < 8; nt++)
#pragma unroll
                for (int jj = 0; jj < 4; jj++) {
                    int scol = s0 + nt * 8 + 2 * c + (jj & 1);
                    int trow = t0 + wq + r + ((jj >> 1) << 3);
                    if (scol > trow) S[nt][jj] = -1e30f;
                }
        }

        // ---- online softmax ----
        float mx0 = -1e30f, mx1 = -1e30f;
#pragma unroll
        for (int nt = 0; nt < 8; nt++) {
            mx0 = fmaxf(mx0, fmaxf(S[nt][0], S[nt][1]));
            mx1 = fmaxf(mx1, fmaxf(S[nt][2], S[nt][3]));
        }
        mx0 = fmaxf(mx0, __shfl_xor_sync(0xffffffffu, mx0, 1));
        mx0 = fmaxf(mx0, __shfl_xor_sync(0xffffffffu, mx0, 2));
        mx1 = fmaxf(mx1, __shfl_xor_sync(0xffffffffu, mx1, 1));
        mx1 = fmaxf(mx1, __shfl_xor_sync(0xffffffffu, mx1, 2));
        float nm0 = fmaxf(m0, mx0), nm1 = fmaxf(m1, mx1);
        float al0 = __expf(m0 - nm0), al1 = __expf(m1 - nm1);
        m0 = nm0; m1 = nm1;
        float su0 = 0.f, su1 = 0.f;
#pragma unroll
        for (int nt = 0; nt < 8; nt++) {
            S[nt][0] = __expf(S[nt][0] - nm0);
            S[nt][1] = __expf(S[nt][1] - nm0);
            S[nt][2] = __expf(S[nt][2] - nm1);
            S[nt][3] = __expf(S[nt][3] - nm1);
            su0 += S[nt][0] + S[nt][1];
            su1 += S[nt][2] + S[nt][3];
        }
        su0 += __shfl_xor_sync(0xffffffffu, su0, 1);
        su0 += __shfl_xor_sync(0xffffffffu, su0, 2);
        su1 += __shfl_xor_sync(0xffffffffu, su1, 1);
        su1 += __shfl_xor_sync(0xffffffffu, su1, 2);
        l0 = l0 * al0 + su0;
        l1 = l1 * al1 + su1;
#pragma unroll
        for (int nt = 0; nt < 8; nt++) {
            O[nt][0] *= al0; O[nt][1] *= al0;
            O[nt][2] *= al1; O[nt][3] *= al1;
        }

        // ---- P to warp-private SMEM (tf32-rounded) ----
#pragma unroll
        for (int nt = 0; nt < 8; nt++) {
            *(float2*)(Pw + r * PPAD + nt * 8 + 2 * c) =
                make_float2(__uint_as_float(to_tf32(S[nt][0])),
                            __uint_as_float(to_tf32(S[nt][1])));
            *(float2*)(Pw + (r + 8) * PPAD + nt * 8 + 2 * c) =
                make_float2(__uint_as_float(to_tf32(S[nt][2])),
                            __uint_as_float(to_tf32(S[nt][3])));
        }
        __syncwarp();

        // ---- O += P V (tf32) ----
#pragma unroll
        for (int ks = 0; ks < 8; ks++) {
            const float* pp = Pw + r * PPAD + ks * 8 + c;
            uint32_t a0 = __float_as_uint(pp[0]);
            uint32_t a2 = __float_as_uint(pp[4]);
            uint32_t a1 = __float_as_uint(pp[8 * PPAD]);
            uint32_t a3 = __float_as_uint(pp[8 * PPAD + 4]);
#pragma unroll
            for (int nt = 0; nt < 8; nt++) {
                const float* vp = Vt + (ks * 8 + c) * VPAD + nt * 8 + r;
                uint32_t b0 = to_tf32(vp[0]);
                uint32_t b1 = to_tf32(vp[4 * VPAD]);
                mma8(O[nt], a0, a1, a2, a3, b0, b1);
            }
        }
        __syncthreads();    // protect K/V buffer reuse next iteration
    }

    // ---- normalize + write ----
    float i0 = 1.f / l0, i1 = 1.f / l1;
    int b = bh >> 4, h = bh & 15;
    int tr0 = t0 + wq + r;
#pragma unroll
    for (int nt = 0; nt < 8; nt++) {
        int col = h * 64 + nt * 8 + 2 * c;
        *(float2*)(attnc + (size_t)(b * TT + tr0) * CC + col) =
            make_float2(O[nt][0] * i0, O[nt][1] * i0);
        *(float2*)(attnc + (size_t)(b * TT + tr0 + 8) * CC + col) =
            make_float2(O[nt][2] * i1, O[nt][3] * i1);
    }
}

// ---------------- transposes --------------------------------------------------
__global__ void transpose_kernel(const float* __restrict__ in, float* __restrict__ out,
                                 int R, int Cc, size_t in_bs, size_t out_bs)
{
    __shared__ float tile[32][33];
    in  += (size_t)blockIdx.z * in_bs;
    out += (size_t)blockIdx.z * out_bs;
    int c0 = blockIdx.x * 32, r0 = blockIdx.y * 32;
    int x = threadIdx.x, y = threadIdx.y;
#pragma unroll
    for (int i = 0; i < 32; i += 8)
        tile[y + i][x] = in[(size_t)(r0 + y + i) * Cc + c0 + x];
    __syncthreads();
#pragma unroll
    for (int i = 0; i < 32; i += 8)
        out[(size_t)(c0 + y + i) * R + r0 + x] = tile[x][y + i];
}

__global__ void transpose_split_kernel(const float* __restrict__ in,
                                       __nv_bfloat16* __restrict__ outH,
                                       __nv_bfloat16* __restrict__ outL,
                                       int R, int Cc, size_t in_bs, size_t out_bs)
{
    __shared__ float tile[32][33];
    in   += (size_t)blockIdx.z * in_bs;
    outH += (size_t)blockIdx.z * out_bs;
    outL += (size_t)blockIdx.z * out_bs;
    int c0 = blockIdx.x * 32, r0 = blockIdx.y * 32;
    int x = threadIdx.x, y = threadIdx.y;
#pragma unroll
    for (int i = 0; i < 32; i += 8)
        tile[y + i][x] = in[(size_t)(r0 + y + i) * Cc + c0 + x];
    __syncthreads();
#pragma unroll
    for (int i = 0; i < 32; i += 8) {
        float vv = tile[x][y + i];
        __nv_bfloat16 hb = __float2bfloat16(vv);
        size_t o = (size_t)(c0 + y + i) * R + r0 + x;
        outH[o] = hb;
        outL[o] = __float2bfloat16(vv - __bfloat162float(hb));
    }
}

// ---------------- block reduction + LayerNorm --------------------------------
__device__ __forceinline__ float blockSumf(float v, float* red) {
    int lane = threadIdx.x & 31, w = threadIdx.x >> 5, nw = blockDim.x >> 5;
    __syncthreads();
#pragma unroll
    for (int o = 16; o > 0; o >>= 1) v += __shfl_xor_sync(0xffffffffu, v, o);
    if (lane == 0) red[w] = v;
    __syncthreads();
    if (w == 0) {
        float t = (lane < nw) ? red[lane] : 0.f;
#pragma unroll
        for (int o = 16; o > 0; o >>= 1) t += __shfl_xor_sync(0xffffffffu, t, o);
        if (lane == 0) red[0] = t;
    }
    __syncthreads();
    return red[0];
}

// MODE 0: fp32 out; MODE 1: bf16 hi/lo out
template <int MODE>
__global__ void __launch_bounds__(256) ln_kernel(
    const float* __restrict__ x, const float* __restrict__ g,
    const float* __restrict__ be, float* __restrict__ outF,
    __nv_bfloat16* __restrict__ outH, __nv_bfloat16* __restrict__ outL)
{
    __shared__ float red[8];
    size_t row = blockIdx.x;
    const float* xr = x + row * CC;
    float v[4], s = 0.f, s2 = 0.f;
#pragma unroll
    for (int i = 0; i < 4; i++) {
        int idx = threadIdx.x + i * 256;
        v[i] = xr[idx];
        s += v[i];
        s2 += v[i] * v[i];
    }
    s  = blockSumf(s, red);
    s2 = blockSumf(s2, red);
    float mu  = s * (1.f / CC);
    float var = s2 * (1.f / CC) - mu * mu;
    float rstd = rsqrtf(var + 1e-5f);
#pragma unroll
    for (int i = 0; i < 4; i++) {
        int idx = threadIdx.x + i * 256;
        float val = (v[i] - mu) * rstd * g[idx] + be[idx];
        if (MODE == 0) {
            outF[row * CC + idx] = val;
        } else {
            __nv_bfloat16 hb = __float2bfloat16(val);
            outH[row * CC + idx] = hb;
            outL[row * CC + idx] = __float2bfloat16(val - __bfloat162float(hb));
        }
    }
}

// ---------------- launch ----------------------------------------------------
extern "C" void kernel_launch(void* const* d_in, const int* in_sizes, int n_in,
                              void* d_out, int out_size)
{
    const float* x   = (const float*)d_in[0];
    const float* Wq  = (const float*)d_in[1];
    const float* Wk  = (const float*)d_in[2];
    const float* Wv  = (const float*)d_in[3];
    const float* Wo  = (const float*)d_in[4];
    const float* bo  = (const float*)d_in[5];
    const float* W1  = (const float*)d_in[6];
    const float* b1  = (const float*)d_in[7];
    const float* W2  = (const float*)d_in[8];
    const float* b2  = (const float*)d_in[9];
    const float* g1  = (const float*)d_in[10];
    const float* be1 = (const float*)d_in[11];
    const float* g2  = (const float*)d_in[12];
    const float* be2 = (const float*)d_in[13];
    float* out = (float*)d_out;

    float *lnF, *q, *v, *attnc, *x1, *ff1, *woT, *w1T, *w2T;
    __nv_bfloat16 *lnH, *lnL, *kH, *kL, *wqkvTH, *wqkvTL;
    cudaGetSymbolAddress((void**)&lnF,    g_lnF);
    cudaGetSymbolAddress((void**)&lnH,    g_lnH);
    cudaGetSymbolAddress((void**)&lnL,    g_lnL);
    cudaGetSymbolAddress((void**)&q,      g_q);
    cudaGetSymbolAddress((void**)&kH,     g_kH);
    cudaGetSymbolAddress((void**)&kL,     g_kL);
    cudaGetSymbolAddress((void**)&v,      g_v);
    cudaGetSymbolAddress((void**)&attnc,  g_attnc);
    cudaGetSymbolAddress((void**)&x1,     g_x1);
    cudaGetSymbolAddress((void**)&ff1,    g_ff1);
    cudaGetSymbolAddress((void**)&wqkvTH, g_wqkvTH);
    cudaGetSymbolAddress((void**)&wqkvTL, g_wqkvTL);
    cudaGetSymbolAddress((void**)&woT,    g_woT);
    cudaGetSymbolAddress((void**)&w1T,    g_w1T);
    cudaGetSymbolAddress((void**)&w2T,    g_w2T);

    cudaFuncSetAttribute(qkv_gemm, cudaFuncAttributeMaxDynamicSharedMemorySize, QSMEM_BYTES);
    cudaFuncSetAttribute(mma_gemm<1024,1024,1>, cudaFuncAttributeMaxDynamicSharedMemorySize, GSMEM_BYTES);
    cudaFuncSetAttribute(mma_gemm<4096,1024,2>, cudaFuncAttributeMaxDynamicSharedMemorySize, GSMEM_BYTES);
    cudaFuncSetAttribute(mma_gemm<1024,4096,1>, cudaFuncAttributeMaxDynamicSharedMemorySize, GSMEM_BYTES);
    cudaFuncSetAttribute(flash_kernel, cudaFuncAttributeMaxDynamicSharedMemorySize, FSMEM_BYTES);

    dim3 tb(32, 8);
    transpose_kernel<<<dim3(32, 32, 1),  tb>>>(Wo, woT, CC, CC, 0, 0);
    transpose_kernel<<<dim3(128, 32, 1), tb>>>(W1, w1T, CC, FFD, 0, 0);
    transpose_kernel<<<dim3(32, 128, 1), tb>>>(W2, w2T, FFD, CC, 0, 0);
    transpose_split_kernel<<<dim3(2, 32, 16), tb>>>(Wq, wqkvTH,           wqkvTL,           CC, DD, (size_t)CC*DD, (size_t)DD*CC);
    transpose_split_kernel<<<dim3(2, 32, 16), tb>>>(Wk, wqkvTH + CC*CC,   wqkvTL + CC*CC,   CC, DD, (size_t)CC*DD, (size_t)DD*CC);
    transpose_split_kernel<<<dim3(2, 32, 16), tb>>>(Wv, wqkvTH + 2*CC*CC, wqkvTL + 2*CC*CC, CC, DD, (size_t)CC*DD, (size_t)DD*CC);

    // 1. LN1 -> bf16 hi/lo
    ln_kernel<1><<<NTOK, 256>>>(x, g1, be1, nullptr, lnH, lnL);
    // 2. fused QKV projection (bf16x3), scatter epilogue (k as bf16 hi/lo)
    qkv_gemm<<<dim3(24, 64), 256, QSMEM_BYTES>>>(
        lnH, lnL, wqkvTH, wqkvTL, q, (uint32_t*)kH, (uint32_t*)kL, v);
    // 3. flash attention -> concat heads
    flash_kernel<<<dim3(16, 64), 256, FSMEM_BYTES>>>(q, kH, kL, v, attnc);
    // 4. x1 = x + attnc @ Wo + bo
    mma_gemm<1024,1024,1><<<dim3(8, 64), 256, GSMEM_BYTES>>>(attnc, woT, x1, bo, x);
    // 5. LN2 -> fp32
    ln_kernel<0><<<NTOK, 256>>>(x1, g2, be2, lnF, nullptr, nullptr);
    // 6. ff1 = relu(ln2 @ W1 + b1)
    mma_gemm<4096,1024,2><<<dim3(32, 64), 256, GSMEM_BYTES>>>(lnF, w1T, ff1, b1, nullptr);
    // 7. out = x1 + ff1 @ W2 + b2
    mma_gemm<1024,4096,1><<<dim3(8, 64), 256, GSMEM_BYTES>>>(ff1, w2T, out, b2, x1);
}

// round 6
// speedup vs baseline: 7.6368x; 1.3520x over previous
#include <cuda_runtime.h>
#include <cuda_fp16.h>
#include <cuda_bf16.h>
#include <cstdint>

// Problem constants
#define BB 4
#define TT 2048
#define CC 1024
#define HH 16
#define DD 64
#define FFD 4096
#define NTOK (BB*TT)          // 8192

// ---------------- scratch (device globals; no allocation allowed) -----------
__device__ uint32_t g_lnH2[NTOK * CC / 2];           // LN2 out, fp16 pairs
__device__ uint32_t g_lnH [NTOK * CC / 2];           // LN1 out, bf16 hi pairs
__device__ uint32_t g_lnL [NTOK * CC / 2];           // LN1 out, bf16 lo pairs
__device__ uint32_t g_qH  [BB*HH * TT * DD / 2];     // Q bf16 hi pairs
__device__ uint32_t g_qL  [BB*HH * TT * DD / 2];
__device__ __nv_bfloat16 g_kH [BB*HH * TT * DD];
__device__ __nv_bfloat16 g_kL [BB*HH * TT * DD];
__device__ __half   g_vT  [BB*HH * DD * TT];         // V fp16 TRANSPOSED [bh][d][t]
__device__ uint32_t g_attnc[NTOK * CC / 2];          // fp16 pairs
__device__ float    g_x1  [NTOK * CC];
__device__ uint32_t g_ff1 [NTOK * FFD / 2];          // fp16 pairs
__device__ __nv_bfloat16 g_wqkvTH[3*CC * CC];
__device__ __nv_bfloat16 g_wqkvTL[3*CC * CC];
__device__ __half   g_woT [CC * CC];
__device__ __half   g_w1T [FFD * CC];
__device__ __half   g_w2T [CC * FFD];

// ---------------- low-level helpers -----------------------------------------
__device__ __forceinline__ uint32_t smem_u32(const void* p) {
    uint32_t a;
    asm("{ .reg .u64 t; cvta.to.shared.u64 t, %1; cvt.u32.u64 %0, t; }"
        : "=r"(a) : "l"(p));
    return a;
}
__device__ __forceinline__ void cp16(uint32_t s, const void* g) {
    asm volatile("cp.async.cg.shared.global [%0], [%1], 16;" :: "r"(s), "l"(g));
}
__device__ __forceinline__ void cpcommit() {
    asm volatile("cp.async.commit_group;" ::: "memory");
}
template <int N>
__device__ __forceinline__ void cpwait() {
    asm volatile("cp.async.wait_group %0;" :: "n"(N) : "memory");
}
// D[4] += A(16x16 bf16) * B(16x8 bf16), m16n8k16
__device__ __forceinline__ void mma16b(float* d, uint32_t a0, uint32_t a1,
                                       uint32_t a2, uint32_t a3,
                                       uint32_t b0, uint32_t b1) {
    asm volatile(
        "mma.sync.aligned.m16n8k16.row.col.f32.bf16.bf16.f32 "
        "{%0,%1,%2,%3}, {%4,%5,%6,%7}, {%8,%9}, {%0,%1,%2,%3};"
        : "+f"(d[0]), "+f"(d[1]), "+f"(d[2]), "+f"(d[3])
        : "r"(a0), "r"(a1), "r"(a2), "r"(a3), "r"(b0), "r"(b1));
}
// D[4] += A(16x16 f16) * B(16x8 f16), m16n8k16
__device__ __forceinline__ void mma16h(float* d, uint32_t a0, uint32_t a1,
                                       uint32_t a2, uint32_t a3,
                                       uint32_t b0, uint32_t b1) {
    asm volatile(
        "mma.sync.aligned.m16n8k16.row.col.f32.f16.f16.f32 "
        "{%0,%1,%2,%3}, {%4,%5,%6,%7}, {%8,%9}, {%0,%1,%2,%3};"
        : "+f"(d[0]), "+f"(d[1]), "+f"(d[2]), "+f"(d[3])
        : "r"(a0), "r"(a1), "r"(a2), "r"(a3), "r"(b0), "r"(b1));
}
__device__ __forceinline__ uint32_t packbf(float x, float y) {
    __nv_bfloat162 t = __floats2bfloat162_rn(x, y);
    return *reinterpret_cast<uint32_t*>(&t);
}
__device__ __forceinline__ uint32_t packh(float x, float y) {
    __half2 t = __floats2half2_rn(x, y);
    return *reinterpret_cast<uint32_t*>(&t);
}
__device__ __forceinline__ void splitbf(float x, float y, uint32_t& hp, uint32_t& lp) {
    float hx = __bfloat162float(__float2bfloat16(x));
    float hy = __bfloat162float(__float2bfloat16(y));
    hp = packbf(hx, hy);
    lp = packbf(x - hx, y - hy);
}

// ================= QKV GEMM: bf16x3, tile 128x128, BK=32, 3 stages ===========
#define QST 3
#define QPADU 20
#define QTILEU (128*QPADU)
#define QSMEM_BYTES (4*QST*QTILEU*4)       // 122880

__global__ void __launch_bounds__(256, 1) qkv_gemm(
    const __nv_bfloat16* __restrict__ AH, const __nv_bfloat16* __restrict__ AL,
    const __nv_bfloat16* __restrict__ BH, const __nv_bfloat16* __restrict__ BL,
    uint32_t* __restrict__ qHo, uint32_t* __restrict__ qLo,
    uint32_t* __restrict__ kHo, uint32_t* __restrict__ kLo,
    __half* __restrict__ vTo)
{
    extern __shared__ uint32_t smq[];
    uint32_t* AHs = smq;
    uint32_t* ALs = smq + QST * QTILEU;
    uint32_t* BHs = smq + 2 * QST * QTILEU;
    uint32_t* BLs = smq + 3 * QST * QTILEU;
    uint32_t aH = smem_u32(AHs), aL = smem_u32(ALs);
    uint32_t bH = smem_u32(BHs), bL = smem_u32(BLs);
    int tid = threadIdx.x, wid = tid >> 5, lane = tid & 31;
    int r = lane >> 2, c = lane & 3;
    int wm = (wid & 1) * 64, wn = (wid >> 1) * 32;
    int row0 = blockIdx.y * 128, col0 = blockIdx.x * 128;

    auto loadst = [&](int slot, int kt) {
        int k0 = kt * 32;
#pragma unroll
        for (int i = 0; i < 2; i++) {
            int j = tid + i * 256;
            int row = j >> 2, ch = j & 3;
            uint32_t doff = (uint32_t)(slot * QTILEU + row * QPADU + ch * 4) * 4;
            size_t sa = (size_t)(row0 + row) * CC + k0 + ch * 8;
            size_t sb = (size_t)(col0 + row) * CC + k0 + ch * 8;
            cp16(aH + doff, AH + sa);
            cp16(aL + doff, AL + sa);
            cp16(bH + doff, BH + sb);
            cp16(bL + doff, BL + sb);
        }
    };

    float acc[4][4][4] = {};
    loadst(0, 0); cpcommit();
    loadst(1, 1); cpcommit();

    for (int kt = 0; kt < 32; kt++) {
        if (kt + 2 < 32) loadst((kt + 2) % QST, kt + 2);
        cpcommit();
        cpwait<2>();
        __syncthreads();
        const uint32_t* AHt = AHs + (kt % QST) * QTILEU;
        const uint32_t* ALt = ALs + (kt % QST) * QTILEU;
        const uint32_t* BHt = BHs + (kt % QST) * QTILEU;
        const uint32_t* BLt = BLs + (kt % QST) * QTILEU;
#pragma unroll
        for (int s = 0; s < 2; s++) {
            int pb = s * 8;
            uint32_t ah[4][4], al[4][4], bh[4][2], bl[4][2];
#pragma unroll
            for (int mt = 0; mt < 4; mt++) {
                int rr = wm + mt * 16;
                ah[mt][0] = AHt[(rr + r) * QPADU + pb + c];
                ah[mt][1] = AHt[(rr + r + 8) * QPADU + pb + c];
                ah[mt][2] = AHt[(rr + r) * QPADU + pb + c + 4];
                ah[mt][3] = AHt[(rr + r + 8) * QPADU + pb + c + 4];
                al[mt][0] = ALt[(rr + r) * QPADU + pb + c];
                al[mt][1] = ALt[(rr + r + 8) * QPADU + pb + c];
                al[mt][2] = ALt[(rr + r) * QPADU + pb + c + 4];
                al[mt][3] = ALt[(rr + r + 8) * QPADU + pb + c + 4];
            }
#pragma unroll
            for (int nt = 0; nt < 4; nt++) {
                int cc_ = wn + nt * 8 + r;
                bh[nt][0] = BHt[cc_ * QPADU + pb + c];
                bh[nt][1] = BHt[cc_ * QPADU + pb + c + 4];
                bl[nt][0] = BLt[cc_ * QPADU + pb + c];
                bl[nt][1] = BLt[cc_ * QPADU + pb + c + 4];
            }
#pragma unroll
            for (int mt = 0; mt < 4; mt++)
#pragma unroll
                for (int nt = 0; nt < 4; nt++) {
                    mma16b(acc[mt][nt], ah[mt][0], ah[mt][1], ah[mt][2], ah[mt][3],
                           bh[nt][0], bh[nt][1]);
                    mma16b(acc[mt][nt], al[mt][0], al[mt][1], al[mt][2], al[mt][3],
                           bh[nt][0], bh[nt][1]);
                    mma16b(acc[mt][nt], ah[mt][0], ah[mt][1], ah[mt][2], ah[mt][3],
                           bl[nt][0], bl[nt][1]);
                }
        }
        __syncthreads();
    }

    // epilogue: scatter q (bf16 H/L), k (bf16 H/L), v (fp16 transposed)
#pragma unroll
    for (int mt = 0; mt < 4; mt++) {
        int rg0 = row0 + wm + mt * 16 + r;
#pragma unroll
        for (int nt = 0; nt < 4; nt++) {
            int cg = col0 + wn + nt * 8 + 2 * c;
            int sel = cg >> 10;
            int h = (cg >> 6) & 15;
            int d = cg & 63;
#pragma unroll
            for (int half_ = 0; half_ < 2; half_++) {
                int rg = rg0 + half_ * 8;
                int bb = rg >> 11, t = rg & 2047;
                float v0 = acc[mt][nt][half_ * 2 + 0];
                float v1 = acc[mt][nt][half_ * 2 + 1];
                int bh_ = bb * HH + h;
                if (sel == 2) {
                    size_t vb = (size_t)bh_ * DD * TT;
                    vTo[vb + (size_t)d * TT + t]       = __float2half(v0);
                    vTo[vb + (size_t)(d + 1) * TT + t] = __float2half(v1);
                } else {
                    size_t ofs = (((size_t)bh_ * TT + t) << 6) + d;
                    uint32_t hp, lp;
                    splitbf(v0, v1, hp, lp);
                    uint32_t* H = (sel == 0) ? qHo : kHo;
                    uint32_t* L = (sel == 0) ? qLo : kLo;
                    H[ofs >> 1] = hp;
                    L[ofs >> 1] = lp;
                }
            }
        }
    }
}

// ================= fp16 GEMM (Wo, W1, W2) ====================================
// C[M,N] = A[M,K] @ BT[N,K]^T, fp16 operands (packed pairs), fp32 accum.
// Tile 128x128, BK=32, 3-stage cp.async. EPI: 1 = +bias+res -> fp32;
// 2 = relu(+bias) -> fp16 packed
#define HST 3
#define HPADU 20
#define HTILEU (128*HPADU)
#define HSMEM_BYTES (2*HST*HTILEU*4)       // 61440

template <int NN, int KK, int EPI>
__global__ void __launch_bounds__(256, 1) hgemm(
    const uint32_t* __restrict__ A, const uint32_t* __restrict__ BT,
    void* __restrict__ Op,
    const float* __restrict__ bias, const float* __restrict__ res)
{
    extern __shared__ uint32_t smh[];
    uint32_t* As = smh;
    uint32_t* Bs = smh + HST * HTILEU;
    uint32_t aS = smem_u32(As), bS = smem_u32(Bs);
    int tid = threadIdx.x, wid = tid >> 5, lane = tid & 31;
    int r = lane >> 2, c = lane & 3;
    int wm = (wid & 1) * 64, wn = (wid >> 1) * 32;
    int row0 = blockIdx.y * 128, col0 = blockIdx.x * 128;
    constexpr int KU = KK / 2;             // u32 per row
    const uint32_t* Ag = A + (size_t)row0 * KU;
    const uint32_t* Bg = BT + (size_t)col0 * KU;

    auto loadst = [&](int slot, int kt) {
        int k0 = kt * 16;                  // u32 offset
#pragma unroll
        for (int i = 0; i < 2; i++) {
            int j = tid + i * 256;         // 0..511
            int row = j >> 2, ch = j & 3;
            uint32_t doff = (uint32_t)(slot * HTILEU + row * HPADU + ch * 4) * 4;
            cp16(aS + doff, Ag + (size_t)row * KU + k0 + ch * 4);
            cp16(bS + doff, Bg + (size_t)row * KU + k0 + ch * 4);
        }
    };

    float acc[4][4][4] = {};
    constexpr int KT = KK / 32;
    loadst(0, 0); cpcommit();
    loadst(1, 1); cpcommit();

    for (int kt = 0; kt < KT; kt++) {
        if (kt + 2 < KT) loadst((kt + 2) % HST, kt + 2);
        cpcommit();
        cpwait<2>();
        __syncthreads();
        const uint32_t* At = As + (kt % HST) * HTILEU;
        const uint32_t* Bt = Bs + (kt % HST) * HTILEU;
#pragma unroll
        for (int s = 0; s < 2; s++) {
            int pb = s * 8;
            uint32_t a[4][4], b[4][2];
#pragma unroll
            for (int mt = 0; mt < 4; mt++) {
                int rr = wm + mt * 16;
                a[mt][0] = At[(rr + r) * HPADU + pb + c];
                a[mt][1] = At[(rr + r + 8) * HPADU + pb + c];
                a[mt][2] = At[(rr + r) * HPADU + pb + c + 4];
                a[mt][3] = At[(rr + r + 8) * HPADU + pb + c + 4];
            }
#pragma unroll
            for (int nt = 0; nt < 4; nt++) {
                int cc_ = wn + nt * 8 + r;
                b[nt][0] = Bt[cc_ * HPADU + pb + c];
                b[nt][1] = Bt[cc_ * HPADU + pb + c + 4];
            }
#pragma unroll
            for (int mt = 0; mt < 4; mt++)
#pragma unroll
                for (int nt = 0; nt < 4; nt++)
                    mma16h(acc[mt][nt], a[mt][0], a[mt][1], a[mt][2], a[mt][3],
                           b[nt][0], b[nt][1]);
        }
        __syncthreads();
    }

#pragma unroll
    for (int mt = 0; mt < 4; mt++) {
        int rg0 = row0 + wm + mt * 16 + r;
#pragma unroll
        for (int nt = 0; nt < 4; nt++) {
            int cg = col0 + wn + nt * 8 + 2 * c;
#pragma unroll
            for (int half_ = 0; half_ < 2; half_++) {
                int rg = rg0 + half_ * 8;
                float v0 = acc[mt][nt][half_ * 2 + 0];
                float v1 = acc[mt][nt][half_ * 2 + 1];
                size_t off = (size_t)rg * NN + cg;
                float2 b2 = *(const float2*)(bias + cg);
                if (EPI == 1) {
                    float2 r2 = *(const float2*)(res + off);
                    *(float2*)((float*)Op + off) =
                        make_float2(v0 + b2.x + r2.x, v1 + b2.y + r2.y);
                } else {
                    ((uint32_t*)Op)[off >> 1] =
                        packh(fmaxf(v0 + b2.x, 0.f), fmaxf(v1 + b2.y, 0.f));
                }
            }
        }
    }
}

// ================= flash attention: bf16x3 QK^T, fp16 PV =====================
#define KPADU 36
#define VPADU 36
#define PPADU 36
#define F_KH 0
#define F_KL 18432
#define F_V  36864
#define F_PS 55296
#define FSMEM_BYTES 73728

__global__ void __launch_bounds__(256, 1) flash_kernel(
    const uint32_t* __restrict__ qH, const uint32_t* __restrict__ qL,
    const __nv_bfloat16* __restrict__ kH, const __nv_bfloat16* __restrict__ kL,
    const uint32_t* __restrict__ vT, uint32_t* __restrict__ attnc)
{
    extern __shared__ char smc[];
    uint32_t base = smem_u32(smc);
    uint32_t* KHs = (uint32_t*)(smc + F_KH);
    uint32_t* KLs = (uint32_t*)(smc + F_KL);
    uint32_t* Vs  = (uint32_t*)(smc + F_V);
    uint32_t* Ps  = (uint32_t*)(smc + F_PS);

    int tid = threadIdx.x, wid = tid >> 5, lane = tid & 31;
    int r = lane >> 2, c = lane & 3;
    int qt = (int)gridDim.x - 1 - (int)blockIdx.x;   // longest blocks first
    int bh = blockIdx.y;
    int t0 = qt * 128;
    int wq = wid * 16;
    const uint32_t* qH32 = qH + (size_t)bh * TT * 32;
    const uint32_t* qL32 = qL + (size_t)bh * TT * 32;
    const __nv_bfloat16* kHb = kH + (size_t)bh * TT * DD;
    const __nv_bfloat16* kLb = kL + (size_t)bh * TT * DD;
    const uint32_t* vT32 = vT + (size_t)bh * DD * (TT / 2);

    // Q fragments direct from global (bf16 hi/lo pairs)
    uint32_t qhp[4][4], qlp[4][4];
#pragma unroll
    for (int s = 0; s < 4; s++) {
        int b0i = (t0 + wq + r) * 32 + 8 * s + c;
        int b1i = (t0 + wq + r + 8) * 32 + 8 * s + c;
        qhp[s][0] = qH32[b0i];     qhp[s][1] = qH32[b1i];
        qhp[s][2] = qH32[b0i + 4]; qhp[s][3] = qH32[b1i + 4];
        qlp[s][0] = qL32[b0i];     qlp[s][1] = qL32[b1i];
        qlp[s][2] = qL32[b0i + 4]; qlp[s][3] = qL32[b1i + 4];
    }

    auto loadkv = [&](int buf, int it) {
        int s0 = it * 64;
        uint32_t kh = base + F_KH + buf * 9216;
        uint32_t kl = base + F_KL + buf * 9216;
        uint32_t vs = base + F_V + buf * 9216;
#pragma unroll
        for (int i = 0; i < 2; i++) {
            int j = tid + i * 256;       // K: 64 rows x 8 chunks of 8 halves
            int row = j >> 3, ch = j & 7;
            uint32_t doff = (uint32_t)(row * KPADU + ch * 4) * 4;
            size_t src = (size_t)(s0 + row) * DD + ch * 8;
            cp16(kh + doff, kHb + src);
            cp16(kl + doff, kLb + src);
        }
#pragma unroll
        for (int i = 0; i < 2; i++) {
            int j = tid + i * 256;       // V: 64 d-rows x 8 chunks of 4 u32
            int row = j >> 3, ch = j & 7;
            cp16(vs + (uint32_t)(row * VPADU + ch * 4) * 4,
                 vT32 + (size_t)row * (TT / 2) + (s0 >> 1) + ch * 4);
        }
    };

    int nst = 2 * qt + 2;
    loadkv(0, 0); cpcommit();

    float m0 = -1e30f, m1 = -1e30f, l0 = 0.f, l1 = 0.f;
    float O[8][4] = {};
    uint32_t* Pw = Ps + wq * PPADU;

    for (int it = 0; it < nst; it++) {
        if (it + 1 < nst) loadkv((it + 1) & 1, it + 1);
        cpcommit();
        cpwait<1>();
        __syncthreads();
        const uint32_t* KHt = KHs + (it & 1) * 2304;   // 9216B / 4
        const uint32_t* KLt = KLs + (it & 1) * 2304;
        const uint32_t* Vt  = Vs  + (it & 1) * 2304;

        // ---- S = Q K^T (bf16x3) ----
        float S[8][4] = {};
#pragma unroll
        for (int s = 0; s < 4; s++) {
#pragma unroll
            for (int nt = 0; nt < 8; nt++) {
                const uint32_t* kp = KHt + (nt * 8 + r) * KPADU + s * 8 + c;
                const uint32_t* lp = KLt + (nt * 8 + r) * KPADU + s * 8 + c;
                uint32_t b0 = kp[0], b1 = kp[4];
                uint32_t l0r = lp[0], l1r = lp[4];
                mma16b(S[nt], qhp[s][0], qhp[s][1], qhp[s][2], qhp[s][3], b0, b1);
                mma16b(S[nt], qlp[s][0], qlp[s][1], qlp[s][2], qlp[s][3], b0, b1);
                mma16b(S[nt], qhp[s][0], qhp[s][1], qhp[s][2], qhp[s][3], l0r, l1r);
            }
        }

        // ---- causal mask ----
        int s0 = it * 64;
        if (s0 + 63 > t0 + wq) {
#pragma unroll
            for (int nt = 0; nt < 8; nt++)
#pragma unroll
                for (int jj = 0; jj < 4; jj++) {
                    int scol = s0 + nt * 8 + 2 * c + (jj & 1);
                    int trow = t0 + wq + r + ((jj >> 1) << 3);
                    if (scol > trow) S[nt][jj] = -1e30f;
                }
        }

        // ---- online softmax ----
        float mx0 = -1e30f, mx1 = -1e30f;
#pragma unroll
        for (int nt = 0; nt < 8; nt++) {
            mx0 = fmaxf(mx0, fmaxf(S[nt][0], S[nt][1]));
            mx1 = fmaxf(mx1, fmaxf(S[nt][2], S[nt][3]));
        }
        mx0 = fmaxf(mx0, __shfl_xor_sync(0xffffffffu, mx0, 1));
        mx0 = fmaxf(mx0, __shfl_xor_sync(0xffffffffu, mx0, 2));
        mx1 = fmaxf(mx1, __shfl_xor_sync(0xffffffffu, mx1, 1));
        mx1 = fmaxf(mx1, __shfl_xor_sync(0xffffffffu, mx1, 2));
        float nm0 = fmaxf(m0, mx0), nm1 = fmaxf(m1, mx1);
        float al0 = __expf(m0 - nm0), al1 = __expf(m1 - nm1);
        m0 = nm0; m1 = nm1;
        float su0 = 0.f, su1 = 0.f;
#pragma unroll
        for (int nt = 0; nt < 8; nt++) {
            S[nt][0] = __expf(S[nt][0] - nm0);
            S[nt][1] = __expf(S[nt][1] - nm0);
            S[nt][2] = __expf(S[nt][2] - nm1);
            S[nt][3] = __expf(S[nt][3] - nm1);
            su0 += S[nt][0] + S[nt][1];
            su1 += S[nt][2] + S[nt][3];
        }
        su0 += __shfl_xor_sync(0xffffffffu, su0, 1);
        su0 += __shfl_xor_sync(0xffffffffu, su0, 2);
        su1 += __shfl_xor_sync(0xffffffffu, su1, 1);
        su1 += __shfl_xor_sync(0xffffffffu, su1, 2);
        l0 = l0 * al0 + su0;
        l1 = l1 * al1 + su1;
#pragma unroll
        for (int nt = 0; nt < 8; nt++) {
            O[nt][0] *= al0; O[nt][1] *= al0;
            O[nt][2] *= al1; O[nt][3] *= al1;
        }

        // ---- P to warp-private SMEM as packed fp16 ----
#pragma unroll
        for (int nt = 0; nt < 8; nt++) {
            Pw[r * PPADU + nt * 4 + c]       = packh(S[nt][0], S[nt][1]);
            Pw[(r + 8) * PPADU + nt * 4 + c] = packh(S[nt][2], S[nt][3]);
        }
        __syncwarp();

        // ---- O += P V (fp16) ----
#pragma unroll
        for (int ks = 0; ks < 4; ks++) {
            uint32_t a0 = Pw[r * PPADU + 8 * ks + c];
            uint32_t a1 = Pw[(r + 8) * PPADU + 8 * ks + c];
            uint32_t a2 = Pw[r * PPADU + 8 * ks + c + 4];
            uint32_t a3 = Pw[(r + 8) * PPADU + 8 * ks + c + 4];
#pragma unroll
            for (int nt = 0; nt < 8; nt++) {
                const uint32_t* vp = Vt + (nt * 8 + r) * VPADU + 8 * ks + c;
                mma16h(O[nt], a0, a1, a2, a3, vp[0], vp[4]);
            }
        }
        __syncthreads();    // protect K/V buffer reuse next iteration
    }

    // ---- normalize + write (fp16 packed) ----
    float i0 = 1.f / l0, i1 = 1.f / l1;
    int b = bh >> 4, h = bh & 15;
    int tr0 = t0 + wq + r;
#pragma unroll
    for (int nt = 0; nt < 8; nt++) {
        int col = h * 64 + nt * 8 + 2 * c;
        attnc[((size_t)(b * TT + tr0) * CC + col) >> 1] =
            packh(O[nt][0] * i0, O[nt][1] * i0);
        attnc[((size_t)(b * TT + tr0 + 8) * CC + col) >> 1] =
            packh(O[nt][2] * i1, O[nt][3] * i1);
    }
}

// ---------------- transposes --------------------------------------------------
__global__ void transpose_h_kernel(const float* __restrict__ in,
                                   __half* __restrict__ out, int R, int Cc)
{
    __shared__ float tile[32][33];
    int c0 = blockIdx.x * 32, r0 = blockIdx.y * 32;
    int x = threadIdx.x, y = threadIdx.y;
#pragma unroll
    for (int i = 0; i < 32; i += 8)
        tile[y + i][x] = in[(size_t)(r0 + y + i) * Cc + c0 + x];
    __syncthreads();
#pragma unroll
    for (int i = 0; i < 32; i += 8)
        out[(size_t)(c0 + y + i) * R + r0 + x] = __float2half(tile[x][y + i]);
}

__global__ void transpose_split_kernel(const float* __restrict__ in,
                                       __nv_bfloat16* __restrict__ outH,
                                       __nv_bfloat16* __restrict__ outL,
                                       int R, int Cc, size_t in_bs, size_t out_bs)
{
    __shared__ float tile[32][33];
    in   += (size_t)blockIdx.z * in_bs;
    outH += (size_t)blockIdx.z * out_bs;
    outL += (size_t)blockIdx.z * out_bs;
    int c0 = blockIdx.x * 32, r0 = blockIdx.y * 32;
    int x = threadIdx.x, y = threadIdx.y;
#pragma unroll
    for (int i = 0; i < 32; i += 8)
        tile[y + i][x] = in[(size_t)(r0 + y + i) * Cc + c0 + x];
    __syncthreads();
#pragma unroll
    for (int i = 0; i < 32; i += 8) {
        float vv = tile[x][y + i];
        __nv_bfloat16 hb = __float2bfloat16(vv);
        size_t o = (size_t)(c0 + y + i) * R + r0 + x;
        outH[o] = hb;
        outL[o] = __float2bfloat16(vv - __bfloat162float(hb));
    }
}

// ---------------- block reduction + LayerNorm --------------------------------
__device__ __forceinline__ float blockSumf(float v, float* red) {
    int lane = threadIdx.x & 31, w = threadIdx.x >> 5, nw = blockDim.x >> 5;
    __syncthreads();
#pragma unroll
    for (int o = 16; o > 0; o >>= 1) v += __shfl_xor_sync(0xffffffffu, v, o);
    if (lane == 0) red[w] = v;
    __syncthreads();
    if (w == 0) {
        float t = (lane < nw) ? red[lane] : 0.f;
#pragma unroll
        for (int o = 16; o > 0; o >>= 1) t += __shfl_xor_sync(0xffffffffu, t, o);
        if (lane == 0) red[0] = t;
    }
    __syncthreads();
    return red[0];
}

// MODE 0: fp16 packed out; MODE 1: bf16 hi/lo packed out
template <int MODE>
__global__ void __launch_bounds__(256) ln_kernel(
    const float* __restrict__ x, const float* __restrict__ g,
    const float* __restrict__ be, uint32_t* __restrict__ outP,
    uint32_t* __restrict__ outH, uint32_t* __restrict__ outL)
{
    __shared__ float red[8];
    size_t row = blockIdx.x;
    const float2* xr = (const float2*)(x + row * CC);
    float2 v[2];
    float s = 0.f, s2 = 0.f;
#pragma unroll
    for (int i = 0; i < 2; i++) {
        int p = threadIdx.x + i * 256;
        v[i] = xr[p];
        s += v[i].x + v[i].y;
        s2 += v[i].x * v[i].x + v[i].y * v[i].y;
    }
    s  = blockSumf(s, red);
    s2 = blockSumf(s2, red);
    float mu  = s * (1.f / CC);
    float var = s2 * (1.f / CC) - mu * mu;
    float rstd = rsqrtf(var + 1e-5f);
#pragma unroll
    for (int i = 0; i < 2; i++) {
        int p = threadIdx.x + i * 256;
        float2 gg = ((const float2*)g)[p];
        float2 bb = ((const float2*)be)[p];
        float a0 = (v[i].x - mu) * rstd * gg.x + bb.x;
        float a1 = (v[i].y - mu) * rstd * gg.y + bb.y;
        if (MODE == 0) {
            outP[row * (CC / 2) + p] = packh(a0, a1);
        } else {
            uint32_t hp, lp;
            splitbf(a0, a1, hp, lp);
            outH[row * (CC / 2) + p] = hp;
            outL[row * (CC / 2) + p] = lp;
        }
    }
}

// ---------------- launch ----------------------------------------------------
extern "C" void kernel_launch(void* const* d_in, const int* in_sizes, int n_in,
                              void* d_out, int out_size)
{
    const float* x   = (const float*)d_in[0];
    const float* Wq  = (const float*)d_in[1];
    const float* Wk  = (const float*)d_in[2];
    const float* Wv  = (const float*)d_in[3];
    const float* Wo  = (const float*)d_in[4];
    const float* bo  = (const float*)d_in[5];
    const float* W1  = (const float*)d_in[6];
    const float* b1  = (const float*)d_in[7];
    const float* W2  = (const float*)d_in[8];
    const float* b2  = (const float*)d_in[9];
    const float* g1  = (const float*)d_in[10];
    const float* be1 = (const float*)d_in[11];
    const float* g2  = (const float*)d_in[12];
    const float* be2 = (const float*)d_in[13];
    float* out = (float*)d_out;

    uint32_t *lnH2, *lnH, *lnL, *qH, *qL, *attnc, *ff1;
    __nv_bfloat16 *kH, *kL, *wqkvTH, *wqkvTL;
    __half *vT, *woT, *w1T, *w2T;
    float *x1;
    cudaGetSymbolAddress((void**)&lnH2,   g_lnH2);
    cudaGetSymbolAddress((void**)&lnH,    g_lnH);
    cudaGetSymbolAddress((void**)&lnL,    g_lnL);
    cudaGetSymbolAddress((void**)&qH,     g_qH);
    cudaGetSymbolAddress((void**)&qL,     g_qL);
    cudaGetSymbolAddress((void**)&kH,     g_kH);
    cudaGetSymbolAddress((void**)&kL,     g_kL);
    cudaGetSymbolAddress((void**)&vT,     g_vT);
    cudaGetSymbolAddress((void**)&attnc,  g_attnc);
    cudaGetSymbolAddress((void**)&x1,     g_x1);
    cudaGetSymbolAddress((void**)&ff1,    g_ff1);
    cudaGetSymbolAddress((void**)&wqkvTH, g_wqkvTH);
    cudaGetSymbolAddress((void**)&wqkvTL, g_wqkvTL);
    cudaGetSymbolAddress((void**)&woT,    g_woT);
    cudaGetSymbolAddress((void**)&w1T,    g_w1T);
    cudaGetSymbolAddress((void**)&w2T,    g_w2T);

    cudaFuncSetAttribute(qkv_gemm, cudaFuncAttributeMaxDynamicSharedMemorySize, QSMEM_BYTES);
    cudaFuncSetAttribute(hgemm<1024,1024,1>, cudaFuncAttributeMaxDynamicSharedMemorySize, HSMEM_BYTES);
    cudaFuncSetAttribute(hgemm<4096,1024,2>, cudaFuncAttributeMaxDynamicSharedMemorySize, HSMEM_BYTES);
    cudaFuncSetAttribute(hgemm<1024,4096,1>, cudaFuncAttributeMaxDynamicSharedMemorySize, HSMEM_BYTES);
    cudaFuncSetAttribute(flash_kernel, cudaFuncAttributeMaxDynamicSharedMemorySize, FSMEM_BYTES);

    dim3 tb(32, 8);
    transpose_h_kernel<<<dim3(32, 32),  tb>>>(Wo, woT, CC, CC);
    transpose_h_kernel<<<dim3(128, 32), tb>>>(W1, w1T, CC, FFD);
    transpose_h_kernel<<<dim3(32, 128), tb>>>(W2, w2T, FFD, CC);
    transpose_split_kernel<<<dim3(2, 32, 16), tb>>>(Wq, wqkvTH,           wqkvTL,           CC, DD, (size_t)CC*DD, (size_t)DD*CC);
    transpose_split_kernel<<<dim3(2, 32, 16), tb>>>(Wk, wqkvTH + CC*CC,   wqkvTL + CC*CC,   CC, DD, (size_t)CC*DD, (size_t)DD*CC);
    transpose_split_kernel<<<dim3(2, 32, 16), tb>>>(Wv, wqkvTH + 2*CC*CC, wqkvTL + 2*CC*CC, CC, DD, (size_t)CC*DD, (size_t)DD*CC);

    // 1. LN1 -> bf16 hi/lo
    ln_kernel<1><<<NTOK, 256>>>(x, g1, be1, nullptr, lnH, lnL);
    // 2. fused QKV projection (bf16x3); epilogue: q bf16 H/L, k bf16 H/L, v fp16^T
    qkv_gemm<<<dim3(24, 64), 256, QSMEM_BYTES>>>(
        (__nv_bfloat16*)lnH, (__nv_bfloat16*)lnL, wqkvTH, wqkvTL,
        qH, qL, (uint32_t*)kH, (uint32_t*)kL, vT);
    // 3. flash attention -> concat heads (fp16)
    flash_kernel<<<dim3(16, 64), 256, FSMEM_BYTES>>>(qH, qL, kH, kL, (uint32_t*)vT, attnc);
    // 4. x1 = x + attnc @ Wo + bo   (fp16 gemm, fp32 out)
    hgemm<1024,1024,1><<<dim3(8, 64), 256, HSMEM_BYTES>>>(
        attnc, (const uint32_t*)woT, x1, bo, x);
    // 5. LN2 -> fp16
    ln_kernel<0><<<NTOK, 256>>>(x1, g2, be2, lnH2, nullptr, nullptr);
    // 6. ff1 = relu(ln2 @ W1 + b1)  (fp16 gemm, fp16 out)
    hgemm<4096,1024,2><<<dim3(32, 64), 256, HSMEM_BYTES>>>(
        lnH2, (const uint32_t*)w1T, ff1, b1, nullptr);
    // 7. out = x1 + ff1 @ W2 + b2   (fp16 gemm, fp32 out)
    hgemm<1024,4096,1><<<dim3(8, 64), 256, HSMEM_BYTES>>>(
        ff1, (const uint32_t*)w2T, out, b2, x1);
}

// round 7
// speedup vs baseline: 8.0515x; 1.0543x over previous
#include <cuda_runtime.h>
#include <cuda_fp16.h>
#include <cuda_bf16.h>
#include <cstdint>

// Problem constants
#define BB 4
#define TT 2048
#define CC 1024
#define HH 16
#define DD 64
#define FFD 4096
#define NTOK (BB*TT)          // 8192

// ---------------- scratch (device globals; no allocation allowed) -----------
__device__ uint32_t g_ln16 [NTOK * CC / 2];          // LN1 out, fp16 pairs
__device__ uint32_t g_lnH2 [NTOK * CC / 2];          // LN2 out, fp16 pairs
__device__ uint32_t g_lnH  [NTOK * CC / 2];          // LN1 out, bf16 hi pairs
__device__ uint32_t g_lnL  [NTOK * CC / 2];          // LN1 out, bf16 lo pairs
__device__ uint32_t g_qH   [BB*HH * TT * DD / 2];    // Q bf16 hi pairs
__device__ uint32_t g_qL   [BB*HH * TT * DD / 2];
__device__ __nv_bfloat16 g_kH [BB*HH * TT * DD];
__device__ __nv_bfloat16 g_kL [BB*HH * TT * DD];
__device__ __half   g_vT   [BB*HH * DD * TT];        // V fp16 TRANSPOSED [bh][d][t]
__device__ uint32_t g_attnc[NTOK * CC / 2];          // fp16 pairs
__device__ float    g_x1   [NTOK * CC];
__device__ uint32_t g_ff1  [NTOK * FFD / 2];         // fp16 pairs
__device__ __nv_bfloat16 g_wqkTH[2*CC * CC];         // Wq^T,Wk^T bf16 hi
__device__ __nv_bfloat16 g_wqkTL[2*CC * CC];
__device__ __half   g_wvT  [CC * CC];                // Wv^T fp16
__device__ __half   g_woT  [CC * CC];
__device__ __half   g_w1T  [FFD * CC];
__device__ __half   g_w2T  [CC * FFD];

// ---------------- low-level helpers -----------------------------------------
__device__ __forceinline__ uint32_t smem_u32(const void* p) {
    uint32_t a;
    asm("{ .reg .u64 t; cvta.to.shared.u64 t, %1; cvt.u32.u64 %0, t; }"
        : "=r"(a) : "l"(p));
    return a;
}
__device__ __forceinline__ void cp16(uint32_t s, const void* g) {
    asm volatile("cp.async.cg.shared.global [%0], [%1], 16;" :: "r"(s), "l"(g));
}
__device__ __forceinline__ void cpcommit() {
    asm volatile("cp.async.commit_group;" ::: "memory");
}
template <int N>
__device__ __forceinline__ void cpwait() {
    asm volatile("cp.async.wait_group %0;" :: "n"(N) : "memory");
}
// D[4] += A(16x16 bf16) * B(16x8 bf16), m16n8k16
__device__ __forceinline__ void mma16b(float* d, uint32_t a0, uint32_t a1,
                                       uint32_t a2, uint32_t a3,
                                       uint32_t b0, uint32_t b1) {
    asm volatile(
        "mma.sync.aligned.m16n8k16.row.col.f32.bf16.bf16.f32 "
        "{%0,%1,%2,%3}, {%4,%5,%6,%7}, {%8,%9}, {%0,%1,%2,%3};"
        : "+f"(d[0]), "+f"(d[1]), "+f"(d[2]), "+f"(d[3])
        : "r"(a0), "r"(a1), "r"(a2), "r"(a3), "r"(b0), "r"(b1));
}
// D[4] += A(16x16 f16) * B(16x8 f16), m16n8k16
__device__ __forceinline__ void mma16h(float* d, uint32_t a0, uint32_t a1,
                                       uint32_t a2, uint32_t a3,
                                       uint32_t b0, uint32_t b1) {
    asm volatile(
        "mma.sync.aligned.m16n8k16.row.col.f32.f16.f16.f32 "
        "{%0,%1,%2,%3}, {%4,%5,%6,%7}, {%8,%9}, {%0,%1,%2,%3};"
        : "+f"(d[0]), "+f"(d[1]), "+f"(d[2]), "+f"(d[3])
        : "r"(a0), "r"(a1), "r"(a2), "r"(a3), "r"(b0), "r"(b1));
}
__device__ __forceinline__ uint32_t packbf(float x, float y) {
    __nv_bfloat162 t = __floats2bfloat162_rn(x, y);
    return *reinterpret_cast<uint32_t*>(&t);
}
__device__ __forceinline__ uint32_t packh(float x, float y) {
    __half2 t = __floats2half2_rn(x, y);
    return *reinterpret_cast<uint32_t*>(&t);
}
__device__ __forceinline__ void splitbf(float x, float y, uint32_t& hp, uint32_t& lp) {
    float hx = __bfloat162float(__float2bfloat16(x));
    float hy = __bfloat162float(__float2bfloat16(y));
    hp = packbf(hx, hy);
    lp = packbf(x - hx, y - hy);
}

// ================= QK GEMM: bf16x3, tile 128x128, BK=32, 3 stages ============
#define QST 3
#define QPADU 20
#define QTILEU (128*QPADU)
#define QSMEM_BYTES (4*QST*QTILEU*4)       // 122880

__global__ void __launch_bounds__(256, 1) qk_gemm(
    const __nv_bfloat16* __restrict__ AH, const __nv_bfloat16* __restrict__ AL,
    const __nv_bfloat16* __restrict__ BH, const __nv_bfloat16* __restrict__ BL,
    uint32_t* __restrict__ qHo, uint32_t* __restrict__ qLo,
    uint32_t* __restrict__ kHo, uint32_t* __restrict__ kLo)
{
    extern __shared__ uint32_t smq[];
    uint32_t* AHs = smq;
    uint32_t* ALs = smq + QST * QTILEU;
    uint32_t* BHs = smq + 2 * QST * QTILEU;
    uint32_t* BLs = smq + 3 * QST * QTILEU;
    uint32_t aH = smem_u32(AHs), aL = smem_u32(ALs);
    uint32_t bH = smem_u32(BHs), bL = smem_u32(BLs);
    int tid = threadIdx.x, wid = tid >> 5, lane = tid & 31;
    int r = lane >> 2, c = lane & 3;
    int wm = (wid & 1) * 64, wn = (wid >> 1) * 32;
    int row0 = blockIdx.y * 128, col0 = blockIdx.x * 128;

    auto loadst = [&](int slot, int kt) {
        int k0 = kt * 32;
#pragma unroll
        for (int i = 0; i < 2; i++) {
            int j = tid + i * 256;
            int row = j >> 2, ch = j & 3;
            uint32_t doff = (uint32_t)(slot * QTILEU + row * QPADU + ch * 4) * 4;
            size_t sa = (size_t)(row0 + row) * CC + k0 + ch * 8;
            size_t sb = (size_t)(col0 + row) * CC + k0 + ch * 8;
            cp16(aH + doff, AH + sa);
            cp16(aL + doff, AL + sa);
            cp16(bH + doff, BH + sb);
            cp16(bL + doff, BL + sb);
        }
    };

    float acc[4][4][4] = {};
    loadst(0, 0); cpcommit();
    loadst(1, 1); cpcommit();

    for (int kt = 0; kt < 32; kt++) {
        if (kt + 2 < 32) loadst((kt + 2) % QST, kt + 2);
        cpcommit();
        cpwait<2>();
        __syncthreads();
        const uint32_t* AHt = AHs + (kt % QST) * QTILEU;
        const uint32_t* ALt = ALs + (kt % QST) * QTILEU;
        const uint32_t* BHt = BHs + (kt % QST) * QTILEU;
        const uint32_t* BLt = BLs + (kt % QST) * QTILEU;
#pragma unroll
        for (int s = 0; s < 2; s++) {
            int pb = s * 8;
            uint32_t ah[4][4], al[4][4], bh[4][2], bl[4][2];
#pragma unroll
            for (int mt = 0; mt < 4; mt++) {
                int rr = wm + mt * 16;
                ah[mt][0] = AHt[(rr + r) * QPADU + pb + c];
                ah[mt][1] = AHt[(rr + r + 8) * QPADU + pb + c];
                ah[mt][2] = AHt[(rr + r) * QPADU + pb + c + 4];
                ah[mt][3] = AHt[(rr + r + 8) * QPADU + pb + c + 4];
                al[mt][0] = ALt[(rr + r) * QPADU + pb + c];
                al[mt][1] = ALt[(rr + r + 8) * QPADU + pb + c];
                al[mt][2] = ALt[(rr + r) * QPADU + pb + c + 4];
                al[mt][3] = ALt[(rr + r + 8) * QPADU + pb + c + 4];
            }
#pragma unroll
            for (int nt = 0; nt < 4; nt++) {
                int cc_ = wn + nt * 8 + r;
                bh[nt][0] = BHt[cc_ * QPADU + pb + c];
                bh[nt][1] = BHt[cc_ * QPADU + pb + c + 4];
                bl[nt][0] = BLt[cc_ * QPADU + pb + c];
                bl[nt][1] = BLt[cc_ * QPADU + pb + c + 4];
            }
#pragma unroll
            for (int mt = 0; mt < 4; mt++)
#pragma unroll
                for (int nt = 0; nt < 4; nt++) {
                    mma16b(acc[mt][nt], ah[mt][0], ah[mt][1], ah[mt][2], ah[mt][3],
                           bh[nt][0], bh[nt][1]);
                    mma16b(acc[mt][nt], al[mt][0], al[mt][1], al[mt][2], al[mt][3],
                           bh[nt][0], bh[nt][1]);
                    mma16b(acc[mt][nt], ah[mt][0], ah[mt][1], ah[mt][2], ah[mt][3],
                           bl[nt][0], bl[nt][1]);
                }
        }
        __syncthreads();
    }

    // epilogue: scatter q (bf16 H/L), k (bf16 H/L)
#pragma unroll
    for (int mt = 0; mt < 4; mt++) {
        int rg0 = row0 + wm + mt * 16 + r;
#pragma unroll
        for (int nt = 0; nt < 4; nt++) {
            int cg = col0 + wn + nt * 8 + 2 * c;
            int sel = cg >> 10;
            int h = (cg >> 6) & 15;
            int d = cg & 63;
            uint32_t* H = sel ? kHo : qHo;
            uint32_t* L = sel ? kLo : qLo;
#pragma unroll
            for (int half_ = 0; half_ < 2; half_++) {
                int rg = rg0 + half_ * 8;
                int bb = rg >> 11, t = rg & 2047;
                size_t ofs = (((size_t)(bb * HH + h) * TT + t) << 6) + d;
                uint32_t hp, lp;
                splitbf(acc[mt][nt][half_ * 2 + 0], acc[mt][nt][half_ * 2 + 1], hp, lp);
                H[ofs >> 1] = hp;
                L[ofs >> 1] = lp;
            }
        }
    }
}

// ================= fp16 GEMM (V-proj, Wo, W1, W2) ============================
// EPI: 1 = +bias+res -> fp32; 2 = relu(+bias) -> fp16 packed; 3 = V^T scatter
#define HST 3
#define HPADU 20
#define HTILEU (128*HPADU)
#define HSMEM_BYTES (2*HST*HTILEU*4)       // 61440

template <int NN, int KK, int EPI>
__global__ void __launch_bounds__(256, 1) hgemm(
    const uint32_t* __restrict__ A, const uint32_t* __restrict__ BT,
    void* __restrict__ Op,
    const float* __restrict__ bias, const float* __restrict__ res)
{
    extern __shared__ uint32_t smh[];
    uint32_t* As = smh;
    uint32_t* Bs = smh + HST * HTILEU;
    uint32_t aS = smem_u32(As), bS = smem_u32(Bs);
    int tid = threadIdx.x, wid = tid >> 5, lane = tid & 31;
    int r = lane >> 2, c = lane & 3;
    int wm = (wid & 1) * 64, wn = (wid >> 1) * 32;
    int row0 = blockIdx.y * 128, col0 = blockIdx.x * 128;
    constexpr int KU = KK / 2;
    const uint32_t* Ag = A + (size_t)row0 * KU;
    const uint32_t* Bg = BT + (size_t)col0 * KU;

    auto loadst = [&](int slot, int kt) {
        int k0 = kt * 16;
#pragma unroll
        for (int i = 0; i < 2; i++) {
            int j = tid + i * 256;
            int row = j >> 2, ch = j & 3;
            uint32_t doff = (uint32_t)(slot * HTILEU + row * HPADU + ch * 4) * 4;
            cp16(aS + doff, Ag + (size_t)row * KU + k0 + ch * 4);
            cp16(bS + doff, Bg + (size_t)row * KU + k0 + ch * 4);
        }
    };

    float acc[4][4][4] = {};
    constexpr int KT = KK / 32;
    loadst(0, 0); cpcommit();
    loadst(1, 1); cpcommit();

    for (int kt = 0; kt < KT; kt++) {
        if (kt + 2 < KT) loadst((kt + 2) % HST, kt + 2);
        cpcommit();
        cpwait<2>();
        __syncthreads();
        const uint32_t* At = As + (kt % HST) * HTILEU;
        const uint32_t* Bt = Bs + (kt % HST) * HTILEU;
#pragma unroll
        for (int s = 0; s < 2; s++) {
            int pb = s * 8;
            uint32_t a[4][4], b[4][2];
#pragma unroll
            for (int mt = 0; mt < 4; mt++) {
                int rr = wm + mt * 16;
                a[mt][0] = At[(rr + r) * HPADU + pb + c];
                a[mt][1] = At[(rr + r + 8) * HPADU + pb + c];
                a[mt][2] = At[(rr + r) * HPADU + pb + c + 4];
                a[mt][3] = At[(rr + r + 8) * HPADU + pb + c + 4];
            }
#pragma unroll
            for (int nt = 0; nt < 4; nt++) {
                int cc_ = wn + nt * 8 + r;
                b[nt][0] = Bt[cc_ * HPADU + pb + c];
                b[nt][1] = Bt[cc_ * HPADU + pb + c + 4];
            }
#pragma unroll
            for (int mt = 0; mt < 4; mt++)
#pragma unroll
                for (int nt = 0; nt < 4; nt++)
                    mma16h(acc[mt][nt], a[mt][0], a[mt][1], a[mt][2], a[mt][3],
                           b[nt][0], b[nt][1]);
        }
        __syncthreads();
    }

#pragma unroll
    for (int mt = 0; mt < 4; mt++) {
        int rg0 = row0 + wm + mt * 16 + r;
#pragma unroll
        for (int nt = 0; nt < 4; nt++) {
            int cg = col0 + wn + nt * 8 + 2 * c;
#pragma unroll
            for (int half_ = 0; half_ < 2; half_++) {
                int rg = rg0 + half_ * 8;
                float v0 = acc[mt][nt][half_ * 2 + 0];
                float v1 = acc[mt][nt][half_ * 2 + 1];
                if (EPI == 3) {
                    int h = cg >> 6, d = cg & 63;
                    int bb = rg >> 11, t = rg & 2047;
                    __half* vp = (__half*)Op +
                        ((size_t)(bb * HH + h) * DD + d) * TT + t;
                    vp[0]  = __float2half(v0);
                    vp[TT] = __float2half(v1);
                } else {
                    size_t off = (size_t)rg * NN + cg;
                    float2 b2 = *(const float2*)(bias + cg);
                    if (EPI == 1) {
                        float2 r2 = *(const float2*)(res + off);
                        *(float2*)((float*)Op + off) =
                            make_float2(v0 + b2.x + r2.x, v1 + b2.y + r2.y);
                    } else {
                        ((uint32_t*)Op)[off >> 1] =
                            packh(fmaxf(v0 + b2.x, 0.f), fmaxf(v1 + b2.y, 0.f));
                    }
                }
            }
        }
    }
}

// ================= flash attention: bf16x3 QK^T, fp16 PV =====================
#define KPADU 36
#define VPADU 36
#define PPADU 36
#define F_KH 0
#define F_KL 18432
#define F_V  36864
#define F_PS 55296
#define FSMEM_BYTES 73728

__global__ void __launch_bounds__(256, 1) flash_kernel(
    const uint32_t* __restrict__ qH, const uint32_t* __restrict__ qL,
    const __nv_bfloat16* __restrict__ kH, const __nv_bfloat16* __restrict__ kL,
    const uint32_t* __restrict__ vT, uint32_t* __restrict__ attnc)
{
    extern __shared__ char smc[];
    uint32_t base = smem_u32(smc);
    uint32_t* KHs = (uint32_t*)(smc + F_KH);
    uint32_t* KLs = (uint32_t*)(smc + F_KL);
    uint32_t* Vs  = (uint32_t*)(smc + F_V);
    uint32_t* Ps  = (uint32_t*)(smc + F_PS);

    int tid = threadIdx.x, wid = tid >> 5, lane = tid & 31;
    int r = lane >> 2, c = lane & 3;
    int qt = (int)gridDim.x - 1 - (int)blockIdx.x;   // longest blocks first
    int bh = blockIdx.y;
    int t0 = qt * 128;
    int wq = wid * 16;
    const uint32_t* qH32 = qH + (size_t)bh * TT * 32;
    const uint32_t* qL32 = qL + (size_t)bh * TT * 32;
    const __nv_bfloat16* kHb = kH + (size_t)bh * TT * DD;
    const __nv_bfloat16* kLb = kL + (size_t)bh * TT * DD;
    const uint32_t* vT32 = vT + (size_t)bh * DD * (TT / 2);

    // Q fragments direct from global (bf16 hi/lo pairs)
    uint32_t qhp[4][4], qlp[4][4];
#pragma unroll
    for (int s = 0; s < 4; s++) {
        int b0i = (t0 + wq + r) * 32 + 8 * s + c;
        int b1i = (t0 + wq + r + 8) * 32 + 8 * s + c;
        qhp[s][0] = qH32[b0i];     qhp[s][1] = qH32[b1i];
        qhp[s][2] = qH32[b0i + 4]; qhp[s][3] = qH32[b1i + 4];
        qlp[s][0] = qL32[b0i];     qlp[s][1] = qL32[b1i];
        qlp[s][2] = qL32[b0i + 4]; qlp[s][3] = qL32[b1i + 4];
    }

    auto loadkv = [&](int buf, int it) {
        int s0 = it * 64;
        uint32_t kh = base + F_KH + buf * 9216;
        uint32_t kl = base + F_KL + buf * 9216;
        uint32_t vs = base + F_V + buf * 9216;
#pragma unroll
        for (int i = 0; i < 2; i++) {
            int j = tid + i * 256;
            int row = j >> 3, ch = j & 7;
            uint32_t doff = (uint32_t)(row * KPADU + ch * 4) * 4;
            size_t src = (size_t)(s0 + row) * DD + ch * 8;
            cp16(kh + doff, kHb + src);
            cp16(kl + doff, kLb + src);
        }
#pragma unroll
        for (int i = 0; i < 2; i++) {
            int j = tid + i * 256;
            int row = j >> 3, ch = j & 7;
            cp16(vs + (uint32_t)(row * VPADU + ch * 4) * 4,
                 vT32 + (size_t)row * (TT / 2) + (s0 >> 1) + ch * 4);
        }
    };

    int nst = 2 * qt + 2;
    loadkv(0, 0); cpcommit();

    float m0 = -1e30f, m1 = -1e30f, l0 = 0.f, l1 = 0.f;
    float O[8][4] = {};
    uint32_t* Pw = Ps + wq * PPADU;

    for (int it = 0; it < nst; it++) {
        if (it + 1 < nst) loadkv((it + 1) & 1, it + 1);
        cpcommit();
        cpwait<1>();
        __syncthreads();
        const uint32_t* KHt = KHs + (it & 1) * 2304;
        const uint32_t* KLt = KLs + (it & 1) * 2304;
        const uint32_t* Vt  = Vs  + (it & 1) * 2304;

        // ---- S = Q K^T (bf16x3) ----
        float S[8][4] = {};
#pragma unroll
        for (int s = 0; s < 4; s++) {
#pragma unroll
            for (int nt = 0; nt < 8; nt++) {
                const uint32_t* kp = KHt + (nt * 8 + r) * KPADU + s * 8 + c;
                const uint32_t* lp = KLt + (nt * 8 + r) * KPADU + s * 8 + c;
                uint32_t b0 = kp[0], b1 = kp[4];
                uint32_t l0r = lp[0], l1r = lp[4];
                mma16b(S[nt], qhp[s][0], qhp[s][1], qhp[s][2], qhp[s][3], b0, b1);
                mma16b(S[nt], qlp[s][0], qlp[s][1], qlp[s][2], qlp[s][3], b0, b1);
                mma16b(S[nt], qhp[s][0], qhp[s][1], qhp[s][2], qhp[s][3], l0r, l1r);
            }
        }

        // ---- causal mask ----
        int s0 = it * 64;
        if (s0 + 63 > t0 + wq) {
#pragma unroll
            for (int nt = 0; nt < 8; nt++)
#pragma unroll
                for (int jj = 0; jj < 4; jj++) {
                    int scol = s0 + nt * 8 + 2 * c + (jj & 1);
                    int trow = t0 + wq + r + ((jj >> 1) << 3);
                    if (scol > trow) S[nt][jj] = -1e30f;
                }
        }

        // ---- online softmax ----
        float mx0 = -1e30f, mx1 = -1e30f;
#pragma unroll
        for (int nt = 0; nt < 8; nt++) {
            mx0 = fmaxf(mx0, fmaxf(S[nt][0], S[nt][1]));
            mx1 = fmaxf(mx1, fmaxf(S[nt][2], S[nt][3]));
        }
        mx0 = fmaxf(mx0, __shfl_xor_sync(0xffffffffu, mx0, 1));
        mx0 = fmaxf(mx0, __shfl_xor_sync(0xffffffffu, mx0, 2));
        mx1 = fmaxf(mx1, __shfl_xor_sync(0xffffffffu, mx1, 1));
        mx1 = fmaxf(mx1, __shfl_xor_sync(0xffffffffu, mx1, 2));
        float nm0 = fmaxf(m0, mx0), nm1 = fmaxf(m1, mx1);
        float al0 = __expf(m0 - nm0), al1 = __expf(m1 - nm1);
        m0 = nm0; m1 = nm1;
        float su0 = 0.f, su1 = 0.f;
#pragma unroll
        for (int nt = 0; nt < 8; nt++) {
            S[nt][0] = __expf(S[nt][0] - nm0);
            S[nt][1] = __expf(S[nt][1] - nm0);
            S[nt][2] = __expf(S[nt][2] - nm1);
            S[nt][3] = __expf(S[nt][3] - nm1);
            su0 += S[nt][0] + S[nt][1];
            su1 += S[nt][2] + S[nt][3];
        }
        su0 += __shfl_xor_sync(0xffffffffu, su0, 1);
        su0 += __shfl_xor_sync(0xffffffffu, su0, 2);
        su1 += __shfl_xor_sync(0xffffffffu, su1, 1);
        su1 += __shfl_xor_sync(0xffffffffu, su1, 2);
        l0 = l0 * al0 + su0;
        l1 = l1 * al1 + su1;
#pragma unroll
        for (int nt = 0; nt < 8; nt++) {
            O[nt][0] *= al0; O[nt][1] *= al0;
            O[nt][2] *= al1; O[nt][3] *= al1;
        }

        // ---- P to warp-private SMEM as packed fp16 ----
#pragma unroll
        for (int nt = 0; nt < 8; nt++) {
            Pw[r * PPADU + nt * 4 + c]       = packh(S[nt][0], S[nt][1]);
            Pw[(r + 8) * PPADU + nt * 4 + c] = packh(S[nt][2], S[nt][3]);
        }
        __syncwarp();

        // ---- O += P V (fp16) ----
#pragma unroll
        for (int ks = 0; ks < 4; ks++) {
            uint32_t a0 = Pw[r * PPADU + 8 * ks + c];
            uint32_t a1 = Pw[(r + 8) * PPADU + 8 * ks + c];
            uint32_t a2 = Pw[r * PPADU + 8 * ks + c + 4];
            uint32_t a3 = Pw[(r + 8) * PPADU + 8 * ks + c + 4];
#pragma unroll
            for (int nt = 0; nt < 8; nt++) {
                const uint32_t* vp = Vt + (nt * 8 + r) * VPADU + 8 * ks + c;
                mma16h(O[nt], a0, a1, a2, a3, vp[0], vp[4]);
            }
        }
        __syncthreads();
    }

    // ---- normalize + write (fp16 packed) ----
    float i0 = 1.f / l0, i1 = 1.f / l1;
    int b = bh >> 4, h = bh & 15;
    int tr0 = t0 + wq + r;
#pragma unroll
    for (int nt = 0; nt < 8; nt++) {
        int col = h * 64 + nt * 8 + 2 * c;
        attnc[((size_t)(b * TT + tr0) * CC + col) >> 1] =
            packh(O[nt][0] * i0, O[nt][1] * i0);
        attnc[((size_t)(b * TT + tr0 + 8) * CC + col) >> 1] =
            packh(O[nt][2] * i1, O[nt][3] * i1);
    }
}

// ---------------- transposes --------------------------------------------------
__global__ void transpose_h_kernel(const float* __restrict__ in,
                                   __half* __restrict__ out, int R, int Cc,
                                   size_t in_bs, size_t out_bs)
{
    __shared__ float tile[32][33];
    in  += (size_t)blockIdx.z * in_bs;
    out += (size_t)blockIdx.z * out_bs;
    int c0 = blockIdx.x * 32, r0 = blockIdx.y * 32;
    int x = threadIdx.x, y = threadIdx.y;
#pragma unroll
    for (int i = 0; i < 32; i += 8)
        tile[y + i][x] = in[(size_t)(r0 + y + i) * Cc + c0 + x];
    __syncthreads();
#pragma unroll
    for (int i = 0; i < 32; i += 8)
        out[(size_t)(c0 + y + i) * R + r0 + x] = __float2half(tile[x][y + i]);
}

__global__ void transpose_split_kernel(const float* __restrict__ in,
                                       __nv_bfloat16* __restrict__ outH,
                                       __nv_bfloat16* __restrict__ outL,
                                       int R, int Cc, size_t in_bs, size_t out_bs)
{
    __shared__ float tile[32][33];
    in   += (size_t)blockIdx.z * in_bs;
    outH += (size_t)blockIdx.z * out_bs;
    outL += (size_t)blockIdx.z * out_bs;
    int c0 = blockIdx.x * 32, r0 = blockIdx.y * 32;
    int x = threadIdx.x, y = threadIdx.y;
#pragma unroll
    for (int i = 0; i < 32; i += 8)
        tile[y + i][x] = in[(size_t)(r0 + y + i) * Cc + c0 + x];
    __syncthreads();
#pragma unroll
    for (int i = 0; i < 32; i += 8) {
        float vv = tile[x][y + i];
        __nv_bfloat16 hb = __float2bfloat16(vv);
        size_t o = (size_t)(c0 + y + i) * R + r0 + x;
        outH[o] = hb;
        outL[o] = __float2bfloat16(vv - __bfloat162float(hb));
    }
}

// ---------------- block reduction + LayerNorm --------------------------------
__device__ __forceinline__ float blockSumf(float v, float* red) {
    int lane = threadIdx.x & 31, w = threadIdx.x >> 5, nw = blockDim.x >> 5;
    __syncthreads();
#pragma unroll
    for (int o = 16; o > 0; o >>= 1) v += __shfl_xor_sync(0xffffffffu, v, o);
    if (lane == 0) red[w] = v;
    __syncthreads();
    if (w == 0) {
        float t = (lane < nw) ? red[lane] : 0.f;
#pragma unroll
        for (int o = 16; o > 0; o >>= 1) t += __shfl_xor_sync(0xffffffffu, t, o);
        if (lane == 0) red[0] = t;
    }
    __syncthreads();
    return red[0];
}

// MODE 0: fp16 packed out only; MODE 1: fp16 + bf16 hi/lo out
template <int MODE>
__global__ void __launch_bounds__(256) ln_kernel(
    const float* __restrict__ x, const float* __restrict__ g,
    const float* __restrict__ be, uint32_t* __restrict__ outP,
    uint32_t* __restrict__ outH, uint32_t* __restrict__ outL)
{
    __shared__ float red[8];
    size_t row = blockIdx.x;
    const float2* xr = (const float2*)(x + row * CC);
    float2 v[2];
    float s = 0.f, s2 = 0.f;
#pragma unroll
    for (int i = 0; i < 2; i++) {
        int p = threadIdx.x + i * 256;
        v[i] = xr[p];
        s += v[i].x + v[i].y;
        s2 += v[i].x * v[i].x + v[i].y * v[i].y;
    }
    s  = blockSumf(s, red);
    s2 = blockSumf(s2, red);
    float mu  = s * (1.f / CC);
    float var = s2 * (1.f / CC) - mu * mu;
    float rstd = rsqrtf(var + 1e-5f);
#pragma unroll
    for (int i = 0; i < 2; i++) {
        int p = threadIdx.x + i * 256;
        float2 gg = ((const float2*)g)[p];
        float2 bb = ((const float2*)be)[p];
        float a0 = (v[i].x - mu) * rstd * gg.x + bb.x;
        float a1 = (v[i].y - mu) * rstd * gg.y + bb.y;
        outP[row * (CC / 2) + p] = packh(a0, a1);
        if (MODE == 1) {
            uint32_t hp, lp;
            splitbf(a0, a1, hp, lp);
            outH[row * (CC / 2) + p] = hp;
            outL[row * (CC / 2) + p] = lp;
        }
    }
}

// ---------------- launch ----------------------------------------------------
extern "C" void kernel_launch(void* const* d_in, const int* in_sizes, int n_in,
                              void* d_out, int out_size)
{
    const float* x   = (const float*)d_in[0];
    const float* Wq  = (const float*)d_in[1];
    const float* Wk  = (const float*)d_in[2];
    const float* Wv  = (const float*)d_in[3];
    const float* Wo  = (const float*)d_in[4];
    const float* bo  = (const float*)d_in[5];
    const float* W1  = (const float*)d_in[6];
    const float* b1  = (const float*)d_in[7];
    const float* W2  = (const float*)d_in[8];
    const float* b2  = (const float*)d_in[9];
    const float* g1  = (const float*)d_in[10];
    const float* be1 = (const float*)d_in[11];
    const float* g2  = (const float*)d_in[12];
    const float* be2 = (const float*)d_in[13];
    float* out = (float*)d_out;

    uint32_t *ln16, *lnH2, *lnH, *lnL, *qH, *qL, *attnc, *ff1;
    __nv_bfloat16 *kH, *kL, *wqkTH, *wqkTL;
    __half *vT, *wvT, *woT, *w1T, *w2T;
    float *x1;
    cudaGetSymbolAddress((void**)&ln16,  g_ln16);
    cudaGetSymbolAddress((void**)&lnH2,  g_lnH2);
    cudaGetSymbolAddress((void**)&lnH,   g_lnH);
    cudaGetSymbolAddress((void**)&lnL,   g_lnL);
    cudaGetSymbolAddress((void**)&qH,    g_qH);
    cudaGetSymbolAddress((void**)&qL,    g_qL);
    cudaGetSymbolAddress((void**)&kH,    g_kH);
    cudaGetSymbolAddress((void**)&kL,    g_kL);
    cudaGetSymbolAddress((void**)&vT,    g_vT);
    cudaGetSymbolAddress((void**)&attnc, g_attnc);
    cudaGetSymbolAddress((void**)&x1,    g_x1);
    cudaGetSymbolAddress((void**)&ff1,   g_ff1);
    cudaGetSymbolAddress((void**)&wqkTH, g_wqkTH);
    cudaGetSymbolAddress((void**)&wqkTL, g_wqkTL);
    cudaGetSymbolAddress((void**)&wvT,   g_wvT);
    cudaGetSymbolAddress((void**)&woT,   g_woT);
    cudaGetSymbolAddress((void**)&w1T,   g_w1T);
    cudaGetSymbolAddress((void**)&w2T,   g_w2T);

    cudaFuncSetAttribute(qk_gemm, cudaFuncAttributeMaxDynamicSharedMemorySize, QSMEM_BYTES);
    cudaFuncSetAttribute(hgemm<1024,1024,1>, cudaFuncAttributeMaxDynamicSharedMemorySize, HSMEM_BYTES);
    cudaFuncSetAttribute(hgemm<1024,1024,3>, cudaFuncAttributeMaxDynamicSharedMemorySize, HSMEM_BYTES);
    cudaFuncSetAttribute(hgemm<4096,1024,2>, cudaFuncAttributeMaxDynamicSharedMemorySize, HSMEM_BYTES);
    cudaFuncSetAttribute(hgemm<1024,4096,1>, cudaFuncAttributeMaxDynamicSharedMemorySize, HSMEM_BYTES);
    cudaFuncSetAttribute(flash_kernel, cudaFuncAttributeMaxDynamicSharedMemorySize, FSMEM_BYTES);

    dim3 tb(32, 8);
    transpose_h_kernel<<<dim3(32, 32, 1),  tb>>>(Wo, woT, CC, CC, 0, 0);
    transpose_h_kernel<<<dim3(128, 32, 1), tb>>>(W1, w1T, CC, FFD, 0, 0);
    transpose_h_kernel<<<dim3(32, 128, 1), tb>>>(W2, w2T, FFD, CC, 0, 0);
    transpose_h_kernel<<<dim3(2, 32, 16),  tb>>>(Wv, wvT, CC, DD, (size_t)CC*DD, (size_t)DD*CC);
    transpose_split_kernel<<<dim3(2, 32, 16), tb>>>(Wq, wqkTH,         wqkTL,         CC, DD, (size_t)CC*DD, (size_t)DD*CC);
    transpose_split_kernel<<<dim3(2, 32, 16), tb>>>(Wk, wqkTH + CC*CC, wqkTL + CC*CC, CC, DD, (size_t)CC*DD, (size_t)DD*CC);

    // 1. LN1 -> fp16 + bf16 hi/lo
    ln_kernel<1><<<NTOK, 256>>>(x, g1, be1, ln16, lnH, lnL);
    // 2a. Q,K projection (bf16x3); epilogue: q/k as bf16 H/L per head
    qk_gemm<<<dim3(16, 64), 256, QSMEM_BYTES>>>(
        (__nv_bfloat16*)lnH, (__nv_bfloat16*)lnL, wqkTH, wqkTL, qH, qL,
        (uint32_t*)kH, (uint32_t*)kL);
    // 2b. V projection (fp16 single); epilogue scatters V^T fp16
    hgemm<1024,1024,3><<<dim3(8, 64), 256, HSMEM_BYTES>>>(
        ln16, (const uint32_t*)wvT, vT, nullptr, nullptr);
    // 3. flash attention -> concat heads (fp16)
    flash_kernel<<<dim3(16, 64), 256, FSMEM_BYTES>>>(qH, qL, kH, kL, (uint32_t*)vT, attnc);
    // 4. x1 = x + attnc @ Wo + bo
    hgemm<1024,1024,1><<<dim3(8, 64), 256, HSMEM_BYTES>>>(
        attnc, (const uint32_t*)woT, x1, bo, x);
    // 5. LN2 -> fp16
    ln_kernel<0><<<NTOK, 256>>>(x1, g2, be2, lnH2, nullptr, nullptr);
    // 6. ff1 = relu(ln2 @ W1 + b1)
    hgemm<4096,1024,2><<<dim3(32, 64), 256, HSMEM_BYTES>>>(
        lnH2, (const uint32_t*)w1T, ff1, b1, nullptr);
    // 7. out = x1 + ff1 @ W2 + b2
    hgemm<1024,4096,1><<<dim3(8, 64), 256, HSMEM_BYTES>>>(
        ff1, (const uint32_t*)w2T, out, b2, x1);
}

// round 8
// speedup vs baseline: 8.5327x; 1.0598x over previous
#include <cuda_runtime.h>
#include <cuda_fp16.h>
#include <cuda_bf16.h>
#include <cstdint>

// Problem constants
#define BB 4
#define TT 2048
#define CC 1024
#define HH 16
#define DD 64
#define FFD 4096
#define NTOK (BB*TT)          // 8192

// ---------------- scratch (device globals; no allocation allowed) -----------
__device__ uint32_t g_ln16 [NTOK * CC / 2];          // LN1 out, fp16 pairs
__device__ uint32_t g_lnH2 [NTOK * CC / 2];          // LN2 out, fp16 pairs
__device__ uint32_t g_lnH  [NTOK * CC / 2];          // LN1 out, bf16 hi pairs
__device__ uint32_t g_lnL  [NTOK * CC / 2];          // LN1 out, bf16 lo pairs
__device__ uint32_t g_qH   [BB*HH * TT * DD / 2];    // Q bf16 hi pairs
__device__ uint32_t g_qL   [BB*HH * TT * DD / 2];
__device__ __nv_bfloat16 g_kH [BB*HH * TT * DD];
__device__ __nv_bfloat16 g_kL [BB*HH * TT * DD];
__device__ __half   g_vT   [BB*HH * DD * TT];        // V fp16 TRANSPOSED [bh][d][t]
__device__ uint32_t g_attnc[NTOK * CC / 2];          // fp16 pairs
__device__ float    g_x1   [NTOK * CC];
__device__ uint32_t g_ff1  [NTOK * FFD / 2];         // fp16 pairs
__device__ __nv_bfloat16 g_wqkTH[2*CC * CC];         // Wq^T,Wk^T bf16 hi
__device__ __nv_bfloat16 g_wqkTL[2*CC * CC];
__device__ __half   g_wvT  [CC * CC];                // Wv^T fp16
__device__ __half   g_woT  [CC * CC];
__device__ __half   g_w1T  [FFD * CC];
__device__ __half   g_w2T  [CC * FFD];

// ---------------- low-level helpers -----------------------------------------
__device__ __forceinline__ uint32_t smem_u32(const void* p) {
    uint32_t a;
    asm("{ .reg .u64 t; cvta.to.shared.u64 t, %1; cvt.u32.u64 %0, t; }"
        : "=r"(a) : "l"(p));
    return a;
}
__device__ __forceinline__ void cp16(uint32_t s, const void* g) {
    asm volatile("cp.async.cg.shared.global [%0], [%1], 16;" :: "r"(s), "l"(g));
}
__device__ __forceinline__ void cpcommit() {
    asm volatile("cp.async.commit_group;" ::: "memory");
}
template <int N>
__device__ __forceinline__ void cpwait() {
    asm volatile("cp.async.wait_group %0;" :: "n"(N) : "memory");
}
// D[4] += A(16x16 bf16) * B(16x8 bf16), m16n8k16
__device__ __forceinline__ void mma16b(float* d, uint32_t a0, uint32_t a1,
                                       uint32_t a2, uint32_t a3,
                                       uint32_t b0, uint32_t b1) {
    asm volatile(
        "mma.sync.aligned.m16n8k16.row.col.f32.bf16.bf16.f32 "
        "{%0,%1,%2,%3}, {%4,%5,%6,%7}, {%8,%9}, {%0,%1,%2,%3};"
        : "+f"(d[0]), "+f"(d[1]), "+f"(d[2]), "+f"(d[3])
        : "r"(a0), "r"(a1), "r"(a2), "r"(a3), "r"(b0), "r"(b1));
}
// D[4] += A(16x16 f16) * B(16x8 f16), m16n8k16
__device__ __forceinline__ void mma16h(float* d, uint32_t a0, uint32_t a1,
                                       uint32_t a2, uint32_t a3,
                                       uint32_t b0, uint32_t b1) {
    asm volatile(
        "mma.sync.aligned.m16n8k16.row.col.f32.f16.f16.f32 "
        "{%0,%1,%2,%3}, {%4,%5,%6,%7}, {%8,%9}, {%0,%1,%2,%3};"
        : "+f"(d[0]), "+f"(d[1]), "+f"(d[2]), "+f"(d[3])
        : "r"(a0), "r"(a1), "r"(a2), "r"(a3), "r"(b0), "r"(b1));
}
__device__ __forceinline__ uint32_t packbf(float x, float y) {
    __nv_bfloat162 t = __floats2bfloat162_rn(x, y);
    return *reinterpret_cast<uint32_t*>(&t);
}
__device__ __forceinline__ uint32_t packh(float x, float y) {
    __half2 t = __floats2half2_rn(x, y);
    return *reinterpret_cast<uint32_t*>(&t);
}
__device__ __forceinline__ void splitbf(float x, float y, uint32_t& hp, uint32_t& lp) {
    float hx = __bfloat162float(__float2bfloat16(x));
    float hy = __bfloat162float(__float2bfloat16(y));
    hp = packbf(hx, hy);
    lp = packbf(x - hx, y - hy);
}

// ================= QK GEMM: bf16x3, tile 128x128, BK=32, 2 stages ============
// 2 stages (81,920 B smem) -> 2 blocks/SM for cross-block latency hiding.
#define QST 2
#define QPADU 20
#define QTILEU (128*QPADU)
#define QSMEM_BYTES (4*QST*QTILEU*4)       // 81920

__global__ void __launch_bounds__(256, 1) qk_gemm(
    const __nv_bfloat16* __restrict__ AH, const __nv_bfloat16* __restrict__ AL,
    const __nv_bfloat16* __restrict__ BH, const __nv_bfloat16* __restrict__ BL,
    uint32_t* __restrict__ qHo, uint32_t* __restrict__ qLo,
    uint32_t* __restrict__ kHo, uint32_t* __restrict__ kLo)
{
    extern __shared__ uint32_t smq[];
    uint32_t* AHs = smq;
    uint32_t* ALs = smq + QST * QTILEU;
    uint32_t* BHs = smq + 2 * QST * QTILEU;
    uint32_t* BLs = smq + 3 * QST * QTILEU;
    uint32_t aH = smem_u32(AHs), aL = smem_u32(ALs);
    uint32_t bH = smem_u32(BHs), bL = smem_u32(BLs);
    int tid = threadIdx.x, wid = tid >> 5, lane = tid & 31;
    int r = lane >> 2, c = lane & 3;
    int wm = (wid & 1) * 64, wn = (wid >> 1) * 32;
    int row0 = blockIdx.y * 128, col0 = blockIdx.x * 128;

    auto loadst = [&](int slot, int kt) {
        int k0 = kt * 32;
#pragma unroll
        for (int i = 0; i < 2; i++) {
            int j = tid + i * 256;
            int row = j >> 2, ch = j & 3;
            uint32_t doff = (uint32_t)(slot * QTILEU + row * QPADU + ch * 4) * 4;
            size_t sa = (size_t)(row0 + row) * CC + k0 + ch * 8;
            size_t sb = (size_t)(col0 + row) * CC + k0 + ch * 8;
            cp16(aH + doff, AH + sa);
            cp16(aL + doff, AL + sa);
            cp16(bH + doff, BH + sb);
            cp16(bL + doff, BL + sb);
        }
    };

    float acc[4][4][4] = {};
    loadst(0, 0); cpcommit();

    for (int kt = 0; kt < 32; kt++) {
        if (kt + 1 < 32) loadst((kt + 1) & 1, kt + 1);
        cpcommit();
        cpwait<1>();
        __syncthreads();
        const uint32_t* AHt = AHs + (kt & 1) * QTILEU;
        const uint32_t* ALt = ALs + (kt & 1) * QTILEU;
        const uint32_t* BHt = BHs + (kt & 1) * QTILEU;
        const uint32_t* BLt = BLs + (kt & 1) * QTILEU;
#pragma unroll
        for (int s = 0; s < 2; s++) {
            int pb = s * 8;
            uint32_t ah[4][4], al[4][4], bh[4][2], bl[4][2];
#pragma unroll
            for (int mt = 0; mt < 4; mt++) {
                int rr = wm + mt * 16;
                ah[mt][0] = AHt[(rr + r) * QPADU + pb + c];
                ah[mt][1] = AHt[(rr + r + 8) * QPADU + pb + c];
                ah[mt][2] = AHt[(rr + r) * QPADU + pb + c + 4];
                ah[mt][3] = AHt[(rr + r + 8) * QPADU + pb + c + 4];
                al[mt][0] = ALt[(rr + r) * QPADU + pb + c];
                al[mt][1] = ALt[(rr + r + 8) * QPADU + pb + c];
                al[mt][2] = ALt[(rr + r) * QPADU + pb + c + 4];
                al[mt][3] = ALt[(rr + r + 8) * QPADU + pb + c + 4];
            }
#pragma unroll
            for (int nt = 0; nt < 4; nt++) {
                int cc_ = wn + nt * 8 + r;
                bh[nt][0] = BHt[cc_ * QPADU + pb + c];
                bh[nt][1] = BHt[cc_ * QPADU + pb + c + 4];
                bl[nt][0] = BLt[cc_ * QPADU + pb + c];
                bl[nt][1] = BLt[cc_ * QPADU + pb + c + 4];
            }
#pragma unroll
            for (int mt = 0; mt < 4; mt++)
#pragma unroll
                for (int nt = 0; nt < 4; nt++) {
                    mma16b(acc[mt][nt], ah[mt][0], ah[mt][1], ah[mt][2], ah[mt][3],
                           bh[nt][0], bh[nt][1]);
                    mma16b(acc[mt][nt], al[mt][0], al[mt][1], al[mt][2], al[mt][3],
                           bh[nt][0], bh[nt][1]);
                    mma16b(acc[mt][nt], ah[mt][0], ah[mt][1], ah[mt][2], ah[mt][3],
                           bl[nt][0], bl[nt][1]);
                }
        }
        __syncthreads();
    }

    // epilogue: scatter q (bf16 H/L), k (bf16 H/L)
#pragma unroll
    for (int mt = 0; mt < 4; mt++) {
        int rg0 = row0 + wm + mt * 16 + r;
#pragma unroll
        for (int nt = 0; nt < 4; nt++) {
            int cg = col0 + wn + nt * 8 + 2 * c;
            int sel = cg >> 10;
            int h = (cg >> 6) & 15;
            int d = cg & 63;
            uint32_t* H = sel ? kHo : qHo;
            uint32_t* L = sel ? kLo : qLo;
#pragma unroll
            for (int half_ = 0; half_ < 2; half_++) {
                int rg = rg0 + half_ * 8;
                int bb = rg >> 11, t = rg & 2047;
                size_t ofs = (((size_t)(bb * HH + h) * TT + t) << 6) + d;
                uint32_t hp, lp;
                splitbf(acc[mt][nt][half_ * 2 + 0], acc[mt][nt][half_ * 2 + 1], hp, lp);
                H[ofs >> 1] = hp;
                L[ofs >> 1] = lp;
            }
        }
    }
}

// ================= fp16 GEMM (V-proj, Wo, W1, W2) ============================
// 4 stages, prefetch distance 2, SINGLE barrier per k-chunk.
// EPI: 1 = +bias+res -> fp32; 2 = relu(+bias) -> fp16 packed; 3 = V^T scatter
#define HST 4
#define HPADU 20
#define HTILEU (128*HPADU)
#define HSMEM_BYTES (2*HST*HTILEU*4)       // 81920

template <int NN, int KK, int EPI>
__global__ void __launch_bounds__(256, 1) hgemm(
    const uint32_t* __restrict__ A, const uint32_t* __restrict__ BT,
    void* __restrict__ Op,
    const float* __restrict__ bias, const float* __restrict__ res)
{
    extern __shared__ uint32_t smh[];
    uint32_t* As = smh;
    uint32_t* Bs = smh + HST * HTILEU;
    uint32_t aS = smem_u32(As), bS = smem_u32(Bs);
    int tid = threadIdx.x, wid = tid >> 5, lane = tid & 31;
    int r = lane >> 2, c = lane & 3;
    int wm = (wid & 1) * 64, wn = (wid >> 1) * 32;
    int row0 = blockIdx.y * 128, col0 = blockIdx.x * 128;
    constexpr int KU = KK / 2;
    const uint32_t* Ag = A + (size_t)row0 * KU;
    const uint32_t* Bg = BT + (size_t)col0 * KU;

    auto loadst = [&](int slot, int kt) {
        int k0 = kt * 16;
#pragma unroll
        for (int i = 0; i < 2; i++) {
            int j = tid + i * 256;
            int row = j >> 2, ch = j & 3;
            uint32_t doff = (uint32_t)(slot * HTILEU + row * HPADU + ch * 4) * 4;
            cp16(aS + doff, Ag + (size_t)row * KU + k0 + ch * 4);
            cp16(bS + doff, Bg + (size_t)row * KU + k0 + ch * 4);
        }
    };

    float acc[4][4][4] = {};
    constexpr int KT = KK / 32;
    loadst(0, 0); cpcommit();
    loadst(1, 1); cpcommit();

    for (int kt = 0; kt < KT; kt++) {
        if (kt + 2 < KT) loadst((kt + 2) & 3, kt + 2);
        cpcommit();
        cpwait<2>();
        __syncthreads();     // single barrier: write stages {kt+2,kt+3} never
                             // alias read stages {kt,kt+1} mod 4 with skew < 1
        const uint32_t* At = As + (kt & 3) * HTILEU;
        const uint32_t* Bt = Bs + (kt & 3) * HTILEU;
#pragma unroll
        for (int s = 0; s < 2; s++) {
            int pb = s * 8;
            uint32_t a[4][4], b[4][2];
#pragma unroll
            for (int mt = 0; mt < 4; mt++) {
                int rr = wm + mt * 16;
                a[mt][0] = At[(rr + r) * HPADU + pb + c];
                a[mt][1] = At[(rr + r + 8) * HPADU + pb + c];
                a[mt][2] = At[(rr + r) * HPADU + pb + c + 4];
                a[mt][3] = At[(rr + r + 8) * HPADU + pb + c + 4];
            }
#pragma unroll
            for (int nt = 0; nt < 4; nt++) {
                int cc_ = wn + nt * 8 + r;
                b[nt][0] = Bt[cc_ * HPADU + pb + c];
                b[nt][1] = Bt[cc_ * HPADU + pb + c + 4];
            }
#pragma unroll
            for (int mt = 0; mt < 4; mt++)
#pragma unroll
                for (int nt = 0; nt < 4; nt++)
                    mma16h(acc[mt][nt], a[mt][0], a[mt][1], a[mt][2], a[mt][3],
                           b[nt][0], b[nt][1]);
        }
    }

#pragma unroll
    for (int mt = 0; mt < 4; mt++) {
        int rg0 = row0 + wm + mt * 16 + r;
#pragma unroll
        for (int nt = 0; nt < 4; nt++) {
            int cg = col0 + wn + nt * 8 + 2 * c;
#pragma unroll
            for (int half_ = 0; half_ < 2; half_++) {
                int rg = rg0 + half_ * 8;
                float v0 = acc[mt][nt][half_ * 2 + 0];
                float v1 = acc[mt][nt][half_ * 2 + 1];
                if (EPI == 3) {
                    int h = cg >> 6, d = cg & 63;
                    int bb = rg >> 11, t = rg & 2047;
                    __half* vp = (__half*)Op +
                        ((size_t)(bb * HH + h) * DD + d) * TT + t;
                    vp[0]  = __float2half(v0);
                    vp[TT] = __float2half(v1);
                } else {
                    size_t off = (size_t)rg * NN + cg;
                    float2 b2 = *(const float2*)(bias + cg);
                    if (EPI == 1) {
                        float2 r2 = *(const float2*)(res + off);
                        *(float2*)((float*)Op + off) =
                            make_float2(v0 + b2.x + r2.x, v1 + b2.y + r2.y);
                    } else {
                        ((uint32_t*)Op)[off >> 1] =
                            packh(fmaxf(v0 + b2.x, 0.f), fmaxf(v1 + b2.y, 0.f));
                    }
                }
            }
        }
    }
}

// ================= flash attention: bf16x3 QK^T, fp16 PV =====================
#define KPADU 36
#define VPADU 36
#define PPADU 36
#define F_KH 0
#define F_KL 18432
#define F_V  36864
#define F_PS 55296
#define FSMEM_BYTES 73728

__global__ void __launch_bounds__(256, 1) flash_kernel(
    const uint32_t* __restrict__ qH, const uint32_t* __restrict__ qL,
    const __nv_bfloat16* __restrict__ kH, const __nv_bfloat16* __restrict__ kL,
    const uint32_t* __restrict__ vT, uint32_t* __restrict__ attnc)
{
    extern __shared__ char smc[];
    uint32_t base = smem_u32(smc);
    uint32_t* KHs = (uint32_t*)(smc + F_KH);
    uint32_t* KLs = (uint32_t*)(smc + F_KL);
    uint32_t* Vs  = (uint32_t*)(smc + F_V);
    uint32_t* Ps  = (uint32_t*)(smc + F_PS);

    int tid = threadIdx.x, wid = tid >> 5, lane = tid & 31;
    int r = lane >> 2, c = lane & 3;
    int qt = (int)gridDim.x - 1 - (int)blockIdx.x;   // longest blocks first
    int bh = blockIdx.y;
    int t0 = qt * 128;
    int wq = wid * 16;
    const uint32_t* qH32 = qH + (size_t)bh * TT * 32;
    const uint32_t* qL32 = qL + (size_t)bh * TT * 32;
    const __nv_bfloat16* kHb = kH + (size_t)bh * TT * DD;
    const __nv_bfloat16* kLb = kL + (size_t)bh * TT * DD;
    const uint32_t* vT32 = vT + (size_t)bh * DD * (TT / 2);

    // Q fragments direct from global (bf16 hi/lo pairs)
    uint32_t qhp[4][4], qlp[4][4];
#pragma unroll
    for (int s = 0; s < 4; s++) {
        int b0i = (t0 + wq + r) * 32 + 8 * s + c;
        int b1i = (t0 + wq + r + 8) * 32 + 8 * s + c;
        qhp[s][0] = qH32[b0i];     qhp[s][1] = qH32[b1i];
        qhp[s][2] = qH32[b0i + 4]; qhp[s][3] = qH32[b1i + 4];
        qlp[s][0] = qL32[b0i];     qlp[s][1] = qL32[b1i];
        qlp[s][2] = qL32[b0i + 4]; qlp[s][3] = qL32[b1i + 4];
    }

    auto loadkv = [&](int buf, int it) {
        int s0 = it * 64;
        uint32_t kh = base + F_KH + buf * 9216;
        uint32_t kl = base + F_KL + buf * 9216;
        uint32_t vs = base + F_V + buf * 9216;
#pragma unroll
        for (int i = 0; i < 2; i++) {
            int j = tid + i * 256;
            int row = j >> 3, ch = j & 7;
            uint32_t doff = (uint32_t)(row * KPADU + ch * 4) * 4;
            size_t src = (size_t)(s0 + row) * DD + ch * 8;
            cp16(kh + doff, kHb + src);
            cp16(kl + doff, kLb + src);
        }
#pragma unroll
        for (int i = 0; i < 2; i++) {
            int j = tid + i * 256;
            int row = j >> 3, ch = j & 7;
            cp16(vs + (uint32_t)(row * VPADU + ch * 4) * 4,
                 vT32 + (size_t)row * (TT / 2) + (s0 >> 1) + ch * 4);
        }
    };

    int nst = 2 * qt + 2;
    loadkv(0, 0); cpcommit();

    float m0 = -1e30f, m1 = -1e30f, l0 = 0.f, l1 = 0.f;
    float O[8][4] = {};
    uint32_t* Pw = Ps + wq * PPADU;

    for (int it = 0; it < nst; it++) {
        if (it + 1 < nst) loadkv((it + 1) & 1, it + 1);
        cpcommit();
        cpwait<1>();
        __syncthreads();
        const uint32_t* KHt = KHs + (it & 1) * 2304;
        const uint32_t* KLt = KLs + (it & 1) * 2304;
        const uint32_t* Vt  = Vs  + (it & 1) * 2304;

        // ---- S = Q K^T (bf16x3) ----
        float S[8][4] = {};
#pragma unroll
        for (int s = 0; s < 4; s++) {
#pragma unroll
            for (int nt = 0; nt < 8; nt++) {
                const uint32_t* kp = KHt + (nt * 8 + r) * KPADU + s * 8 + c;
                const uint32_t* lp = KLt + (nt * 8 + r) * KPADU + s * 8 + c;
                uint32_t b0 = kp[0], b1 = kp[4];
                uint32_t l0r = lp[0], l1r = lp[4];
                mma16b(S[nt], qhp[s][0], qhp[s][1], qhp[s][2], qhp[s][3], b0, b1);
                mma16b(S[nt], qlp[s][0], qlp[s][1], qlp[s][2], qlp[s][3], b0, b1);
                mma16b(S[nt], qhp[s][0], qhp[s][1], qhp[s][2], qhp[s][3], l0r, l1r);
            }
        }

        // ---- causal mask ----
        int s0 = it * 64;
        if (s0 + 63 > t0 + wq) {
#pragma unroll
            for (int nt = 0; nt < 8; nt++)
#pragma unroll
                for (int jj = 0; jj < 4; jj++) {
                    int scol = s0 + nt * 8 + 2 * c + (jj & 1);
                    int trow = t0 + wq + r + ((jj >> 1) << 3);
                    if (scol > trow) S[nt][jj] = -1e30f;
                }
        }

        // ---- online softmax ----
        float mx0 = -1e30f, mx1 = -1e30f;
#pragma unroll
        for (int nt = 0; nt < 8; nt++) {
            mx0 = fmaxf(mx0, fmaxf(S[nt][0], S[nt][1]));
            mx1 = fmaxf(mx1, fmaxf(S[nt][2], S[nt][3]));
        }
        mx0 = fmaxf(mx0, __shfl_xor_sync(0xffffffffu, mx0, 1));
        mx0 = fmaxf(mx0, __shfl_xor_sync(0xffffffffu, mx0, 2));
        mx1 = fmaxf(mx1, __shfl_xor_sync(0xffffffffu, mx1, 1));
        mx1 = fmaxf(mx1, __shfl_xor_sync(0xffffffffu, mx1, 2));
        float nm0 = fmaxf(m0, mx0), nm1 = fmaxf(m1, mx1);
        float al0 = __expf(m0 - nm0), al1 = __expf(m1 - nm1);
        m0 = nm0; m1 = nm1;
        float su0 = 0.f, su1 = 0.f;
#pragma unroll
        for (int nt = 0; nt < 8; nt++) {
            S[nt][0] = __expf(S[nt][0] - nm0);
            S[nt][1] = __expf(S[nt][1] - nm0);
            S[nt][2] = __expf(S[nt][2] - nm1);
            S[nt][3] = __expf(S[nt][3] - nm1);
            su0 += S[nt][0] + S[nt][1];
            su1 += S[nt][2] + S[nt][3];
        }
        su0 += __shfl_xor_sync(0xffffffffu, su0, 1);
        su0 += __shfl_xor_sync(0xffffffffu, su0, 2);
        su1 += __shfl_xor_sync(0xffffffffu, su1, 1);
        su1 += __shfl_xor_sync(0xffffffffu, su1, 2);
        l0 = l0 * al0 + su0;
        l1 = l1 * al1 + su1;
#pragma unroll
        for (int nt = 0; nt < 8; nt++) {
            O[nt][0] *= al0; O[nt][1] *= al0;
            O[nt][2] *= al1; O[nt][3] *= al1;
        }

        // ---- P to warp-private SMEM as packed fp16 ----
#pragma unroll
        for (int nt = 0; nt < 8; nt++) {
            Pw[r * PPADU + nt * 4 + c]       = packh(S[nt][0], S[nt][1]);
            Pw[(r + 8) * PPADU + nt * 4 + c] = packh(S[nt][2], S[nt][3]);
        }
        __syncwarp();

        // ---- O += P V (fp16) ----
#pragma unroll
        for (int ks = 0; ks < 4; ks++) {
            uint32_t a0 = Pw[r * PPADU + 8 * ks + c];
            uint32_t a1 = Pw[(r + 8) * PPADU + 8 * ks + c];
            uint32_t a2 = Pw[r * PPADU + 8 * ks + c + 4];
            uint32_t a3 = Pw[(r + 8) * PPADU + 8 * ks + c + 4];
#pragma unroll
            for (int nt = 0; nt < 8; nt++) {
                const uint32_t* vp = Vt + (nt * 8 + r) * VPADU + 8 * ks + c;
                mma16h(O[nt], a0, a1, a2, a3, vp[0], vp[4]);
            }
        }
        __syncthreads();
    }

    // ---- normalize + write (fp16 packed) ----
    float i0 = 1.f / l0, i1 = 1.f / l1;
    int b = bh >> 4, h = bh & 15;
    int tr0 = t0 + wq + r;
#pragma unroll
    for (int nt = 0; nt < 8; nt++) {
        int col = h * 64 + nt * 8 + 2 * c;
        attnc[((size_t)(b * TT + tr0) * CC + col) >> 1] =
            packh(O[nt][0] * i0, O[nt][1] * i0);
        attnc[((size_t)(b * TT + tr0 + 8) * CC + col) >> 1] =
            packh(O[nt][2] * i1, O[nt][3] * i1);
    }
}

// ---------------- transposes --------------------------------------------------
__global__ void transpose_h_kernel(const float* __restrict__ in,
                                   __half* __restrict__ out, int R, int Cc,
                                   size_t in_bs, size_t out_bs)
{
    __shared__ float tile[32][33];
    in  += (size_t)blockIdx.z * in_bs;
    out += (size_t)blockIdx.z * out_bs;
    int c0 = blockIdx.x * 32, r0 = blockIdx.y * 32;
    int x = threadIdx.x, y = threadIdx.y;
#pragma unroll
    for (int i = 0; i < 32; i += 8)
        tile[y + i][x] = in[(size_t)(r0 + y + i) * Cc + c0 + x];
    __syncthreads();
#pragma unroll
    for (int i = 0; i < 32; i += 8)
        out[(size_t)(c0 + y + i) * R + r0 + x] = __float2half(tile[x][y + i]);
}

__global__ void transpose_split_kernel(const float* __restrict__ in,
                                       __nv_bfloat16* __restrict__ outH,
                                       __nv_bfloat16* __restrict__ outL,
                                       int R, int Cc, size_t in_bs, size_t out_bs)
{
    __shared__ float tile[32][33];
    in   += (size_t)blockIdx.z * in_bs;
    outH += (size_t)blockIdx.z * out_bs;
    outL += (size_t)blockIdx.z * out_bs;
    int c0 = blockIdx.x * 32, r0 = blockIdx.y * 32;
    int x = threadIdx.x, y = threadIdx.y;
#pragma unroll
    for (int i = 0; i < 32; i += 8)
        tile[y + i][x] = in[(size_t)(r0 + y + i) * Cc + c0 + x];
    __syncthreads();
#pragma unroll
    for (int i = 0; i < 32; i += 8) {
        float vv = tile[x][y + i];
        __nv_bfloat16 hb = __float2bfloat16(vv);
        size_t o = (size_t)(c0 + y + i) * R + r0 + x;
        outH[o] = hb;
        outL[o] = __float2bfloat16(vv - __bfloat162float(hb));
    }
}

// ---------------- block reduction + LayerNorm --------------------------------
__device__ __forceinline__ float blockSumf(float v, float* red) {
    int lane = threadIdx.x & 31, w = threadIdx.x >> 5, nw = blockDim.x >> 5;
    __syncthreads();
#pragma unroll
    for (int o = 16; o > 0; o >>= 1) v += __shfl_xor_sync(0xffffffffu, v, o);
    if (lane == 0) red[w] = v;
    __syncthreads();
    if (w == 0) {
        float t = (lane < nw) ? red[lane] : 0.f;
#pragma unroll
        for (int o = 16; o > 0; o >>= 1) t += __shfl_xor_sync(0xffffffffu, t, o);
        if (lane == 0) red[0] = t;
    }
    __syncthreads();
    return red[0];
}

// MODE 0: fp16 packed out only; MODE 1: fp16 + bf16 hi/lo out
template <int MODE>
__global__ void __launch_bounds__(256) ln_kernel(
    const float* __restrict__ x, const float* __restrict__ g,
    const float* __restrict__ be, uint32_t* __restrict__ outP,
    uint32_t* __restrict__ outH, uint32_t* __restrict__ outL)
{
    __shared__ float red[8];
    size_t row = blockIdx.x;
    const float2* xr = (const float2*)(x + row * CC);
    float2 v[2];
    float s = 0.f, s2 = 0.f;
#pragma unroll
    for (int i = 0; i < 2; i++) {
        int p = threadIdx.x + i * 256;
        v[i] = xr[p];
        s += v[i].x + v[i].y;
        s2 += v[i].x * v[i].x + v[i].y * v[i].y;
    }
    s  = blockSumf(s, red);
    s2 = blockSumf(s2, red);
    float mu  = s * (1.f / CC);
    float var = s2 * (1.f / CC) - mu * mu;
    float rstd = rsqrtf(var + 1e-5f);
#pragma unroll
    for (int i = 0; i < 2; i++) {
        int p = threadIdx.x + i * 256;
        float2 gg = ((const float2*)g)[p];
        float2 bb = ((const float2*)be)[p];
        float a0 = (v[i].x - mu) * rstd * gg.x + bb.x;
        float a1 = (v[i].y - mu) * rstd * gg.y + bb.y;
        outP[row * (CC / 2) + p] = packh(a0, a1);
        if (MODE == 1) {
            uint32_t hp, lp;
            splitbf(a0, a1, hp, lp);
            outH[row * (CC / 2) + p] = hp;
            outL[row * (CC / 2) + p] = lp;
        }
    }
}

// ---------------- launch ----------------------------------------------------
extern "C" void kernel_launch(void* const* d_in, const int* in_sizes, int n_in,
                              void* d_out, int out_size)
{
    const float* x   = (const float*)d_in[0];
    const float* Wq  = (const float*)d_in[1];
    const float* Wk  = (const float*)d_in[2];
    const float* Wv  = (const float*)d_in[3];
    const float* Wo  = (const float*)d_in[4];
    const float* bo  = (const float*)d_in[5];
    const float* W1  = (const float*)d_in[6];
    const float* b1  = (const float*)d_in[7];
    const float* W2  = (const float*)d_in[8];
    const float* b2  = (const float*)d_in[9];
    const float* g1  = (const float*)d_in[10];
    const float* be1 = (const float*)d_in[11];
    const float* g2  = (const float*)d_in[12];
    const float* be2 = (const float*)d_in[13];
    float* out = (float*)d_out;

    uint32_t *ln16, *lnH2, *lnH, *lnL, *qH, *qL, *attnc, *ff1;
    __nv_bfloat16 *kH, *kL, *wqkTH, *wqkTL;
    __half *vT, *wvT, *woT, *w1T, *w2T;
    float *x1;
    cudaGetSymbolAddress((void**)&ln16,  g_ln16);
    cudaGetSymbolAddress((void**)&lnH2,  g_lnH2);
    cudaGetSymbolAddress((void**)&lnH,   g_lnH);
    cudaGetSymbolAddress((void**)&lnL,   g_lnL);
    cudaGetSymbolAddress((void**)&qH,    g_qH);
    cudaGetSymbolAddress((void**)&qL,    g_qL);
    cudaGetSymbolAddress((void**)&kH,    g_kH);
    cudaGetSymbolAddress((void**)&kL,    g_kL);
    cudaGetSymbolAddress((void**)&vT,    g_vT);
    cudaGetSymbolAddress((void**)&attnc, g_attnc);
    cudaGetSymbolAddress((void**)&x1,    g_x1);
    cudaGetSymbolAddress((void**)&ff1,   g_ff1);
    cudaGetSymbolAddress((void**)&wqkTH, g_wqkTH);
    cudaGetSymbolAddress((void**)&wqkTL, g_wqkTL);
    cudaGetSymbolAddress((void**)&wvT,   g_wvT);
    cudaGetSymbolAddress((void**)&woT,   g_woT);
    cudaGetSymbolAddress((void**)&w1T,   g_w1T);
    cudaGetSymbolAddress((void**)&w2T,   g_w2T);

    cudaFuncSetAttribute(qk_gemm, cudaFuncAttributeMaxDynamicSharedMemorySize, QSMEM_BYTES);
    cudaFuncSetAttribute(hgemm<1024,1024,1>, cudaFuncAttributeMaxDynamicSharedMemorySize, HSMEM_BYTES);
    cudaFuncSetAttribute(hgemm<1024,1024,3>, cudaFuncAttributeMaxDynamicSharedMemorySize, HSMEM_BYTES);
    cudaFuncSetAttribute(hgemm<4096,1024,2>, cudaFuncAttributeMaxDynamicSharedMemorySize, HSMEM_BYTES);
    cudaFuncSetAttribute(hgemm<1024,4096,1>, cudaFuncAttributeMaxDynamicSharedMemorySize, HSMEM_BYTES);
    cudaFuncSetAttribute(flash_kernel, cudaFuncAttributeMaxDynamicSharedMemorySize, FSMEM_BYTES);

    dim3 tb(32, 8);
    // Launch order chosen so launch #3 (0-indexed) is qk_gemm (ncu profiles it).
    // 0. LN1 -> fp16 + bf16 hi/lo
    ln_kernel<1><<<NTOK, 256>>>(x, g1, be1, ln16, lnH, lnL);
    // 1-2. Wq/Wk transpose+split
    transpose_split_kernel<<<dim3(2, 32, 16), tb>>>(Wq, wqkTH,         wqkTL,         CC, DD, (size_t)CC*DD, (size_t)DD*CC);
    transpose_split_kernel<<<dim3(2, 32, 16), tb>>>(Wk, wqkTH + CC*CC, wqkTL + CC*CC, CC, DD, (size_t)CC*DD, (size_t)DD*CC);
    // 3. Q,K projection (bf16x3)    <-- profiled launch
    qk_gemm<<<dim3(16, 64), 256, QSMEM_BYTES>>>(
        (__nv_bfloat16*)lnH, (__nv_bfloat16*)lnL, wqkTH, wqkTL, qH, qL,
        (uint32_t*)kH, (uint32_t*)kL);
    // 4. Wv transpose (fp16)
    transpose_h_kernel<<<dim3(2, 32, 16), tb>>>(Wv, wvT, CC, DD, (size_t)CC*DD, (size_t)DD*CC);
    // 5. V projection (fp16 single) -> V^T fp16
    hgemm<1024,1024,3><<<dim3(8, 64), 256, HSMEM_BYTES>>>(
        ln16, (const uint32_t*)wvT, vT, nullptr, nullptr);
    // 6. flash attention -> concat heads (fp16)
    flash_kernel<<<dim3(16, 64), 256, FSMEM_BYTES>>>(qH, qL, kH, kL, (uint32_t*)vT, attnc);
    // 7. Wo transpose
    transpose_h_kernel<<<dim3(32, 32, 1), tb>>>(Wo, woT, CC, CC, 0, 0);
    // 8. x1 = x + attnc @ Wo + bo
    hgemm<1024,1024,1><<<dim3(8, 64), 256, HSMEM_BYTES>>>(
        attnc, (const uint32_t*)woT, x1, bo, x);
    // 9. LN2 -> fp16
    ln_kernel<0><<<NTOK, 256>>>(x1, g2, be2, lnH2, nullptr, nullptr);
    // 10. W1 transpose
    transpose_h_kernel<<<dim3(128, 32, 1), tb>>>(W1, w1T, CC, FFD, 0, 0);
    // 11. ff1 = relu(ln2 @ W1 + b1)
    hgemm<4096,1024,2><<<dim3(32, 64), 256, HSMEM_BYTES>>>(
        lnH2, (const uint32_t*)w1T, ff1, b1, nullptr);
    // 12. W2 transpose
    transpose_h_kernel<<<dim3(32, 128, 1), tb>>>(W2, w2T, FFD, CC, 0, 0);
    // 13. out = x1 + ff1 @ W2 + b2
    hgemm<1024,4096,1><<<dim3(8, 64), 256, HSMEM_BYTES>>>(
        ff1, (const uint32_t*)w2T, out, b2, x1);
}